// round 11
// baseline (speedup 1.0000x reference)
#include <cuda_runtime.h>
#include <math.h>
#include <stdint.h>

#define BDIM 256
#define IDIM 256
#define HDIM 512
#define SDIM 64
#define GE 2048   // 4*H
#define GD 1024   // 4*I

// ---------------- scratch (device globals: allocation-free contract) ----------
__device__ float g_xT[SDIM * BDIM * IDIM];            // x transposed (S,B,I), tf32-rounded
__device__ float g_Gx[(size_t)SDIM * BDIM * GE];      // x@Wih^T + biases (fp32)
// Whh tiled+rounded: [s][bh(32)][stage(16)][64 rows (gate*16+hc)][36 (32 K + 4 pad)]
__device__ float g_Wt2[(size_t)SDIM * 32 * 16 * 64 * 36];
__device__ float g_hA[BDIM * HDIM];                   // hidden fp32 ping
__device__ float g_hB[BDIM * HDIM];                   // hidden fp32 pong
// hidden tf32 tiled: [bm(4)][stage(16)][64 rows][36]
__device__ float g_hT3A[4 * 16 * 64 * 36];
__device__ float g_hT3B[4 * 16 * 64 * 36];
__device__ float g_enc[SDIM * BDIM * HDIM];           // elu(enc)
__device__ float g_dg[(size_t)SDIM * BDIM * 768];     // decoder gates (i,g,o)
__device__ float g_hd[SDIM * BDIM * IDIM];            // decoder hd
// grid barrier state (relative comparisons -> replay-safe)
__device__ unsigned g_bar_cnt;
__device__ volatile unsigned g_bar_gen;

__device__ __forceinline__ float sigf(float x) { return 1.0f / (1.0f + expf(-x)); }

__device__ __forceinline__ float to_tf32(float x) {
    uint32_t u;
    asm("cvt.rna.tf32.f32 %0, %1;" : "=r"(u) : "f"(x));
    return __uint_as_float(u);
}
__device__ __forceinline__ float4 cvt4(float4 v) {
    return make_float4(to_tf32(v.x), to_tf32(v.y), to_tf32(v.z), to_tf32(v.w));
}

__device__ __forceinline__ void mma8(float c[4], uint32_t a0, uint32_t a1,
                                     uint32_t a2, uint32_t a3,
                                     uint32_t b0, uint32_t b1) {
    asm volatile(
        "mma.sync.aligned.m16n8k8.row.col.f32.tf32.tf32.f32 "
        "{%0,%1,%2,%3}, {%4,%5,%6,%7}, {%8,%9}, {%0,%1,%2,%3};\n"
        : "+f"(c[0]), "+f"(c[1]), "+f"(c[2]), "+f"(c[3])
        : "r"(a0), "r"(a1), "r"(a2), "r"(a3), "r"(b0), "r"(b1));
}
__device__ __forceinline__ uint32_t fbits(float x) { return __float_as_uint(x); }
__device__ __forceinline__ uint32_t frna(float x) { return fbits(to_tf32(x)); }

__device__ __forceinline__ void cpa16(uint32_t dst, const void* src) {
    asm volatile("cp.async.cg.shared.global [%0], [%1], 16;\n" :: "r"(dst), "l"(src));
}
__device__ __forceinline__ void cpa_commit() {
    asm volatile("cp.async.commit_group;\n");
}
template <int N>
__device__ __forceinline__ void cpa_wait() {
    asm volatile("cp.async.wait_group %0;\n" :: "n"(N));
}

// ---------------- bulk-copy + mbarrier helpers --------------------------------
__device__ __forceinline__ void mbar_init(uint32_t mbar, uint32_t cnt) {
    asm volatile("mbarrier.init.shared.b64 [%0], %1;" :: "r"(mbar), "r"(cnt) : "memory");
}
__device__ __forceinline__ void mbar_expect_tx(uint32_t mbar, uint32_t bytes) {
    asm volatile("mbarrier.arrive.expect_tx.shared.b64 _, [%0], %1;"
                 :: "r"(mbar), "r"(bytes) : "memory");
}
__device__ __forceinline__ void mbar_wait(uint32_t mbar, uint32_t parity) {
    asm volatile(
        "{\n\t"
        ".reg .pred P1;\n\t"
        "WAIT_LOOP_%=:\n\t"
        "mbarrier.try_wait.parity.acquire.cta.shared::cta.b64 P1, [%0], %1, 0x989680;\n\t"
        "@P1 bra.uni WAIT_DONE_%=;\n\t"
        "bra.uni WAIT_LOOP_%=;\n\t"
        "WAIT_DONE_%=:\n\t"
        "}"
        :: "r"(mbar), "r"(parity) : "memory");
}
__device__ __forceinline__ void bulk_g2s(uint32_t dst, const void* src,
                                         uint32_t bytes, uint32_t mbar) {
    asm volatile(
        "cp.async.bulk.shared::cluster.global.mbarrier::complete_tx::bytes [%0], [%1], %2, [%3];"
        :: "r"(dst), "l"(src), "r"(bytes), "r"(mbar) : "memory");
}

// ---------------- device-wide barrier (128 CTAs, all co-resident) -------------
__device__ __forceinline__ void grid_bar() {
    __threadfence();          // make this thread's writes GPU-visible
    __syncthreads();          // all CTA threads' writes ordered before arrival
    if (threadIdx.x == 0) {
        unsigned gen = g_bar_gen;
        if (atomicAdd(&g_bar_cnt, 1) == 127u) {
            g_bar_cnt = 0;
            __threadfence();
            g_bar_gen = gen + 1;
        } else {
            while (g_bar_gen == gen) { }
        }
        __threadfence();      // acquire: order peer writes before our reads
        asm volatile("fence.proxy.async;" ::: "memory");  // generic->async proxy
    }
    __syncthreads();
}

// ---------------- Whh -> tiled tf32 layout ------------------------------------
__global__ __launch_bounds__(256) void k_cvt_whh2(const float* __restrict__ W) {
    int s  = blockIdx.y;
    int bh = blockIdx.x >> 4;
    int st = blockIdx.x & 15;
    float* dst = g_Wt2 + (((size_t)s * 32 + bh) * 16 + st) * 2304;
#pragma unroll
    for (int j = 0; j < 9; j++) {
        int idx = j * 256 + threadIdx.x;   // 0..2303
        int r = idx / 36;
        int c = idx - r * 36;
        float v = 0.0f;
        if (c < 32) {
            int grow = ((r >> 4) << 9) + bh * 16 + (r & 15);  // gate*512 + hcol
            v = to_tf32(W[((size_t)s * GE + grow) * HDIM + st * 32 + c]);
        }
        dst[idx] = v;
    }
}

// ---------------- x (B,I,S) -> xT (S,B,I), tf32-rounded ----------------------
__global__ __launch_bounds__(256) void k_transpose_x(const float* __restrict__ x) {
    __shared__ float tile[32][65];
    int b  = blockIdx.x >> 3;
    int i0 = (blockIdx.x & 7) * 32;
    int tid = threadIdx.x;
    int s = tid & 63, it = tid >> 6;
#pragma unroll
    for (int j = 0; j < 8; j++) {
        int i = it * 8 + j;
        tile[i][s] = x[(b * IDIM + i0 + i) * SDIM + s];
    }
    __syncthreads();
    int i2 = tid & 31, sq = tid >> 5;
#pragma unroll
    for (int j = 0; j < 8; j++) {
        int ss = sq * 8 + j;
        g_xT[(ss * BDIM + b) * IDIM + i0 + i2] = to_tf32(tile[i2][ss]);
    }
}

__global__ void k_zero_h() {
    int i = blockIdx.x * 256 + threadIdx.x;   // grid 576*256 = 147456
    if (i < BDIM * HDIM) g_hA[i] = 0.0f;
    g_hT3A[i] = 0.0f;
}

// ---------------- Gx[s] = xT[s] @ Wih^T + biases  (CTA 128x128, warp 32x64) ---
__global__ __launch_bounds__(256) void k_gx(const float* __restrict__ Wih,
                                            const float* __restrict__ bih,
                                            const float* __restrict__ bhh) {
    __shared__ float sm[2 * 5120];
    int tid = threadIdx.x;
    int s = blockIdx.y;
    int bm = blockIdx.x & 1;
    int bn = blockIdx.x >> 1;

    const float* Ag[2]; const float* Bg[2];
    uint32_t aoff[2], boff[2];
#pragma unroll
    for (int jj = 0; jj < 2; jj++) {
        int q = tid + 256 * jj;
        int r = q >> 2, kq = q & 3;
        Ag[jj] = g_xT + (size_t)(s * BDIM + bm * 128 + r) * IDIM + kq * 4;
        Bg[jj] = Wih + ((size_t)s * GE + bn * 128 + r) * IDIM + kq * 4;
        aoff[jj] = (uint32_t)(r * 20 + kq * 4) * 4;
        boff[jj] = (uint32_t)(2560 + r * 20 + kq * 4) * 4;
    }
    uint32_t sbase = (uint32_t)__cvta_generic_to_shared(sm);

    int warp = tid >> 5, lane = tid & 31;
    int g = lane >> 2, t = lane & 3;
    int m0 = (warp >> 1) * 32, n0 = (warp & 1) * 64;

    float c[2][8][4] = {};

    cpa16(sbase + aoff[0], Ag[0]); cpa16(sbase + aoff[1], Ag[1]);
    cpa16(sbase + boff[0], Bg[0]); cpa16(sbase + boff[1], Bg[1]);
    cpa_commit();

    for (int st = 0; st < 16; st++) {
        if (st + 1 < 16) {
            uint32_t so = sbase + ((st + 1) & 1) * 5120 * 4;
            cpa16(so + aoff[0], Ag[0] + (st + 1) * 16);
            cpa16(so + aoff[1], Ag[1] + (st + 1) * 16);
            cpa16(so + boff[0], Bg[0] + (st + 1) * 16);
            cpa16(so + boff[1], Bg[1] + (st + 1) * 16);
            cpa_commit();
            cpa_wait<1>();
        } else {
            cpa_wait<0>();
        }
        __syncthreads();
        int fb = (st & 1) * 5120;
#pragma unroll
        for (int kk = 0; kk < 16; kk += 8) {
            uint32_t b0[8], b1[8];
#pragma unroll
            for (int f = 0; f < 8; f++) {
                b0[f] = frna(sm[fb + 2560 + (n0 + f * 8 + g) * 20 + kk + t]);
                b1[f] = frna(sm[fb + 2560 + (n0 + f * 8 + g) * 20 + kk + t + 4]);
            }
#pragma unroll
            for (int dm = 0; dm < 2; dm++) {
                int r0 = m0 + dm * 16 + g;
                uint32_t a0 = fbits(sm[fb + r0 * 20 + kk + t]);
                uint32_t a1 = fbits(sm[fb + (r0 + 8) * 20 + kk + t]);
                uint32_t a2 = fbits(sm[fb + r0 * 20 + kk + t + 4]);
                uint32_t a3 = fbits(sm[fb + (r0 + 8) * 20 + kk + t + 4]);
#pragma unroll
                for (int f = 0; f < 8; f++)
                    mma8(c[dm][f], a0, a1, a2, a3, b0[f], b1[f]);
            }
        }
        __syncthreads();
    }
#pragma unroll
    for (int f = 0; f < 8; f++) {
        int col = bn * 128 + n0 + f * 8 + 2 * t;
        float bi0 = bih[s * GE + col] + bhh[s * GE + col];
        float bi1 = bih[s * GE + col + 1] + bhh[s * GE + col + 1];
#pragma unroll
        for (int dm = 0; dm < 2; dm++) {
            int row = bm * 128 + m0 + dm * 16 + g;
            size_t r0 = ((size_t)s * BDIM + row) * GE + col;
            size_t r1 = ((size_t)s * BDIM + row + 8) * GE + col;
            *(float2*)&g_Gx[r0] = make_float2(c[dm][f][0] + bi0, c[dm][f][1] + bi1);
            *(float2*)&g_Gx[r1] = make_float2(c[dm][f][2] + bi0, c[dm][f][3] + bi1);
        }
    }
}

// ---------------- persistent encoder: all 64 steps in one kernel --------------
// grid 128 = bm(4 x 64 rows) x bh(32 x [4 gates x 16 hc]); all CTAs co-resident.
// Per step: 16 K-stages of 32 via cp.async.bulk 4-slot mbarrier ring
// (each slot: A 64x36 + B 64x36). Device-wide barrier between steps.
#define ESLOT 4608   // floats per ring slot
__global__ __launch_bounds__(256) void k_enc_all() {
    extern __shared__ float sm[];
    __shared__ uint64_t mbar_s[4];
    int tid = threadIdx.x;
    int bm = blockIdx.x & 3;
    int bh = blockIdx.x >> 2;

    uint32_t smb = (uint32_t)__cvta_generic_to_shared(sm);
    uint32_t mb0 = (uint32_t)__cvta_generic_to_shared(mbar_s);

    if (tid == 0) {
#pragma unroll
        for (int p = 0; p < 4; p++) mbar_init(mb0 + p * 8, 1);
    }
    __syncthreads();

    int warp = tid >> 5, lane = tid & 31;
    int m0 = (warp >> 2) * 32;
    int n0 = (warp & 3) * 16;
    int g = lane >> 2, t = lane & 3;

    for (int s = 0; s < SDIM; s++) {
        const float* hT3in = (s & 1) ? g_hT3B : g_hT3A;
        float* hT3out      = (s & 1) ? g_hT3A : g_hT3B;
        const float* hin   = (s & 1) ? g_hB : g_hA;
        float* hout        = (s & 1) ? g_hA : g_hB;
        const float* Abase = hT3in + (size_t)bm * 16 * 2304;
        const float* Bbase = g_Wt2 + (((size_t)s * 32 + bh) * 16) * 2304;

        if (tid == 0) {
#pragma unroll
            for (int p = 0; p < 4; p++) {
                uint32_t mb = mb0 + p * 8;
                mbar_expect_tx(mb, 18432);
                bulk_g2s(smb + p * ESLOT * 4,        Abase + p * 2304, 9216, mb);
                bulk_g2s(smb + p * ESLOT * 4 + 9216, Bbase + p * 2304, 9216, mb);
            }
        }

        float c[2][2][4] = {};

        for (int st = 0; st < 16; st++) {
            mbar_wait(mb0 + (st & 3) * 8, (st >> 2) & 1);
            int ab = (st & 3) * ESLOT;
            int bb = ab + 2304;
#pragma unroll
            for (int kc = 0; kc < 32; kc += 8) {
                uint32_t b0[2], b1[2];
#pragma unroll
                for (int f = 0; f < 2; f++) {
                    int rb = n0 + f * 8 + g;
                    b0[f] = fbits(sm[bb + rb * 36 + kc + t]);
                    b1[f] = fbits(sm[bb + rb * 36 + kc + t + 4]);
                }
#pragma unroll
                for (int dm = 0; dm < 2; dm++) {
                    int r0 = m0 + dm * 16 + g;
                    uint32_t a0 = fbits(sm[ab + r0 * 36 + kc + t]);
                    uint32_t a1 = fbits(sm[ab + (r0 + 8) * 36 + kc + t]);
                    uint32_t a2 = fbits(sm[ab + r0 * 36 + kc + t + 4]);
                    uint32_t a3 = fbits(sm[ab + (r0 + 8) * 36 + kc + t + 4]);
#pragma unroll
                    for (int f = 0; f < 2; f++)
                        mma8(c[dm][f], a0, a1, a2, a3, b0[f], b1[f]);
                }
            }
            __syncthreads();
            if (tid == 0 && st + 4 < 16) {
                uint32_t mb = mb0 + (st & 3) * 8;
                mbar_expect_tx(mb, 18432);
                bulk_g2s(smb + (st & 3) * ESLOT * 4,        Abase + (st + 4) * 2304, 9216, mb);
                bulk_g2s(smb + (st & 3) * ESLOT * 4 + 9216, Bbase + (st + 4) * 2304, 9216, mb);
            }
        }

        // accumulators -> Cs (64 x 68; aliases slot 0, free after final stage)
#pragma unroll
        for (int dm = 0; dm < 2; dm++)
#pragma unroll
        for (int f = 0; f < 2; f++) {
            int col0 = n0 + f * 8 + 2 * t;
            *(float2*)&sm[(m0 + dm * 16 + g) * 68 + col0]     = make_float2(c[dm][f][0], c[dm][f][1]);
            *(float2*)&sm[(m0 + dm * 16 + g + 8) * 68 + col0] = make_float2(c[dm][f][2], c[dm][f][3]);
        }
        __syncthreads();

        // fused LSTM pointwise + elu: 4 elems/thread (64 rows x 16 hcols)
        int row = tid >> 2;
        int hc0 = (tid & 3) * 4;
        int grow = bm * 64 + row;
        int gcol = bh * 16 + hc0;
        const float* Gxp = g_Gx + ((size_t)s * BDIM + grow) * GE + gcol;
        float4 gi = *(float4*)&sm[row * 68 + 0 * 16 + hc0];
        float4 gf = *(float4*)&sm[row * 68 + 1 * 16 + hc0];
        float4 gg = *(float4*)&sm[row * 68 + 2 * 16 + hc0];
        float4 go = *(float4*)&sm[row * 68 + 3 * 16 + hc0];
        float4 xi = *(const float4*)(Gxp + 0 * HDIM);
        float4 xf = *(const float4*)(Gxp + 1 * HDIM);
        float4 xg = *(const float4*)(Gxp + 2 * HDIM);
        float4 xo = *(const float4*)(Gxp + 3 * HDIM);
        float4 hp = *(const float4*)&hin[(size_t)grow * HDIM + gcol];
        float4 hv, tv, ev;
#pragma unroll
        for (int q = 0; q < 4; q++) {
            float vi = (&gi.x)[q] + (&xi.x)[q];
            float vf = (&gf.x)[q] + (&xf.x)[q];
            float vg = (&gg.x)[q] + (&xg.x)[q];
            float vo = (&go.x)[q] + (&xo.x)[q];
            float cc = sigf(vf) * (&hp.x)[q] + sigf(vi) * tanhf(vg);
            float hn = sigf(vo) * tanhf(cc);
            (&hv.x)[q] = hn;
            (&tv.x)[q] = to_tf32(hn);
            (&ev.x)[q] = hn > 0.0f ? hn : expm1f(hn);
        }
        *(float4*)&hout[(size_t)grow * HDIM + gcol] = hv;
        *(float4*)&g_enc[(size_t)s * BDIM * HDIM + (size_t)grow * HDIM + gcol] = ev;
        size_t tvo = ((size_t)(bm * 16 + (bh >> 1)) * 64 + row) * 36 + (bh & 1) * 16 + hc0;
        *(float4*)&hT3out[tvo] = tv;

        if (s < SDIM - 1) grid_bar();
    }
}

// ---------------- strided residual chain --------------------------------------
__global__ void k_chain() {
    int e = blockIdx.x * 256 + threadIdx.x;
    float prev = g_enc[60 * BDIM * HDIM + e];
#pragma unroll
    for (int k = 0; k < 16; k++) {
        int off = (k * 4) * BDIM * HDIM + e;
        float v = 0.5f * g_enc[off] + 0.5f * prev;
        g_enc[off] = v;
        prev = v;
    }
}

// ---------------- decoder GEMM: enc_rev @ Wih_dec^T (i,g,o), big tiles --------
__global__ __launch_bounds__(256) void k_dec_gemm(const float* __restrict__ Wd) {
    __shared__ float sm[2 * 5120];
    int tid = threadIdx.x;
    int sd = blockIdx.y;
    int bm = blockIdx.x & 1;
    int bn = blockIdx.x >> 1;
    const int agate[3] = {0, 2, 3};
    int grow0 = agate[bn >> 1] * IDIM + (bn & 1) * 128;

    const float* Ag[2]; const float* Bg[2];
    uint32_t aoff[2], boff[2];
#pragma unroll
    for (int jj = 0; jj < 2; jj++) {
        int q = tid + 256 * jj;
        int r = q >> 2, kq = q & 3;
        Ag[jj] = g_enc + ((size_t)(63 - sd) * BDIM + bm * 128 + r) * HDIM + kq * 4;
        Bg[jj] = Wd + ((size_t)sd * GD + grow0 + r) * HDIM + kq * 4;
        aoff[jj] = (uint32_t)(r * 20 + kq * 4) * 4;
        boff[jj] = (uint32_t)(2560 + r * 20 + kq * 4) * 4;
    }
    uint32_t sbase = (uint32_t)__cvta_generic_to_shared(sm);

    int warp = tid >> 5, lane = tid & 31;
    int g = lane >> 2, t = lane & 3;
    int m0 = (warp >> 1) * 32, n0 = (warp & 1) * 64;

    float c[2][8][4] = {};

    cpa16(sbase + aoff[0], Ag[0]); cpa16(sbase + aoff[1], Ag[1]);
    cpa16(sbase + boff[0], Bg[0]); cpa16(sbase + boff[1], Bg[1]);
    cpa_commit();

    for (int st = 0; st < 32; st++) {
        if (st + 1 < 32) {
            uint32_t so = sbase + ((st + 1) & 1) * 5120 * 4;
            cpa16(so + aoff[0], Ag[0] + (st + 1) * 16);
            cpa16(so + aoff[1], Ag[1] + (st + 1) * 16);
            cpa16(so + boff[0], Bg[0] + (st + 1) * 16);
            cpa16(so + boff[1], Bg[1] + (st + 1) * 16);
            cpa_commit();
            cpa_wait<1>();
        } else {
            cpa_wait<0>();
        }
        __syncthreads();
        int fb = (st & 1) * 5120;
#pragma unroll
        for (int kk = 0; kk < 16; kk += 8) {
            uint32_t b0[8], b1[8];
#pragma unroll
            for (int f = 0; f < 8; f++) {
                b0[f] = frna(sm[fb + 2560 + (n0 + f * 8 + g) * 20 + kk + t]);
                b1[f] = frna(sm[fb + 2560 + (n0 + f * 8 + g) * 20 + kk + t + 4]);
            }
#pragma unroll
            for (int dm = 0; dm < 2; dm++) {
                int r0 = m0 + dm * 16 + g;
                uint32_t a0 = frna(sm[fb + r0 * 20 + kk + t]);
                uint32_t a1 = frna(sm[fb + (r0 + 8) * 20 + kk + t]);
                uint32_t a2 = frna(sm[fb + r0 * 20 + kk + t + 4]);
                uint32_t a3 = frna(sm[fb + (r0 + 8) * 20 + kk + t + 4]);
#pragma unroll
                for (int f = 0; f < 8; f++)
                    mma8(c[dm][f], a0, a1, a2, a3, b0[f], b1[f]);
            }
        }
        __syncthreads();
    }
#pragma unroll
    for (int f = 0; f < 8; f++) {
        int col = bn * 128 + n0 + f * 8 + 2 * t;
#pragma unroll
        for (int dm = 0; dm < 2; dm++) {
            int row = bm * 128 + m0 + dm * 16 + g;
            size_t r0 = ((size_t)sd * BDIM + row) * 768 + col;
            size_t r1 = ((size_t)sd * BDIM + row + 8) * 768 + col;
            *(float2*)&g_dg[r0] = make_float2(c[dm][f][0], c[dm][f][1]);
            *(float2*)&g_dg[r1] = make_float2(c[dm][f][2], c[dm][f][3]);
        }
    }
}

// ---------------- decoder pointwise: biases + activations ---------------------
__global__ __launch_bounds__(256) void k_dec_pw(const float* __restrict__ bid,
                                                const float* __restrict__ bhd) {
    int idx = blockIdx.x * 256 + threadIdx.x;
    int icg = idx & 63;
    int row = (idx >> 6) & 255;
    int sd  = idx >> 14;
    int ic  = icg * 4;
    size_t base = ((size_t)sd * BDIM + row) * 768;
    float4 vi = *(const float4*)&g_dg[base + 0 * IDIM + ic];
    float4 vg = *(const float4*)&g_dg[base + 1 * IDIM + ic];
    float4 vo = *(const float4*)&g_dg[base + 2 * IDIM + ic];
    const float* B1 = bid + sd * GD;
    const float* B2 = bhd + sd * GD;
    float4 bi1 = *(const float4*)&B1[0 * IDIM + ic];
    float4 bi2 = *(const float4*)&B2[0 * IDIM + ic];
    float4 bg1 = *(const float4*)&B1[2 * IDIM + ic];
    float4 bg2 = *(const float4*)&B2[2 * IDIM + ic];
    float4 bo1 = *(const float4*)&B1[3 * IDIM + ic];
    float4 bo2 = *(const float4*)&B2[3 * IDIM + ic];
    float4 ov;
#pragma unroll
    for (int q = 0; q < 4; q++) {
        float gi = (&vi.x)[q] + (&bi1.x)[q] + (&bi2.x)[q];
        float gg = (&vg.x)[q] + (&bg1.x)[q] + (&bg2.x)[q];
        float go = (&vo.x)[q] + (&bo1.x)[q] + (&bo2.x)[q];
        float cc = sigf(gi) * tanhf(gg);
        (&ov.x)[q] = sigf(go) * tanhf(cc);
    }
    *(float4*)&g_hd[((size_t)sd * BDIM + row) * IDIM + ic] = ov;
}

// ---------------- cumsum(4) + tanh + reverse + transpose to (B,I,S) -----------
__global__ void k_final(float* __restrict__ out) {
    int idx = blockIdx.x * 256 + threadIdx.x;
    int i = idx & 255;
    int q = (idx >> 8) & 15;
    int b = idx >> 12;
    int base = (4 * q * BDIM + b) * IDIM + i;
    float a0 = g_hd[base];
    float a1 = g_hd[base + 1 * BDIM * IDIM];
    float a2 = g_hd[base + 2 * BDIM * IDIM];
    float a3 = g_hd[base + 3 * BDIM * IDIM];
    float r0 = a0, r1 = r0 + a1, r2 = r1 + a2, r3 = r2 + a3;
    float4 v = make_float4(tanhf(r3), tanhf(r2), tanhf(r1), tanhf(r0));
    *(float4*)(out + (size_t)(b * IDIM + i) * SDIM + (60 - 4 * q)) = v;
}

// ---------------- launch ------------------------------------------------------
extern "C" void kernel_launch(void* const* d_in, const int* in_sizes, int n_in,
                              void* d_out, int out_size) {
    const float* x       = (const float*)d_in[0];
    const float* Wih_enc = (const float*)d_in[1];
    const float* Whh_enc = (const float*)d_in[2];
    const float* bih_enc = (const float*)d_in[3];
    const float* bhh_enc = (const float*)d_in[4];
    const float* Wih_dec = (const float*)d_in[5];
    // d_in[6] = Whh_dec: unused by the reference computation
    const float* bih_dec = (const float*)d_in[7];
    const float* bhh_dec = (const float*)d_in[8];
    float* out = (float*)d_out;

    cudaFuncSetAttribute(k_enc_all, cudaFuncAttributeMaxDynamicSharedMemorySize,
                         4 * ESLOT * 4);

    k_cvt_whh2<<<dim3(512, 64), 256>>>(Whh_enc);
    k_transpose_x<<<2048, 256>>>(x);
    k_zero_h<<<576, 256>>>();
    k_gx<<<dim3(32, 64), 256>>>(Wih_enc, bih_enc, bhh_enc);
    k_enc_all<<<128, 256, 4 * ESLOT * 4>>>();
    k_chain<<<512, 256>>>();
    k_dec_gemm<<<dim3(12, 64), 256>>>(Wih_dec);
    k_dec_pw<<<4096, 256>>>(bih_dec, bhh_dec);
    k_final<<<4096, 256>>>(out);
}

// round 12
// speedup vs baseline: 1.0284x; 1.0284x over previous
#include <cuda_runtime.h>
#include <math.h>
#include <stdint.h>

#define BDIM 256
#define IDIM 256
#define HDIM 512
#define SDIM 64
#define GE 2048   // 4*H
#define GD 1024   // 4*I

// ---------------- scratch (device globals: allocation-free contract) ----------
__device__ float g_xT[SDIM * BDIM * IDIM];            // x transposed (S,B,I), tf32-rounded
__device__ float g_Gx[(size_t)SDIM * BDIM * GE];      // x@Wih^T + biases (fp32)
// Whh tiled+rounded: [s][bh(32)][stage(16)][64 rows (gate*16+hc)][36 (32 K + 4 pad)]
__device__ float g_Wt2[(size_t)SDIM * 32 * 16 * 64 * 36];
__device__ float g_hA[BDIM * HDIM];                   // hidden fp32 ping
__device__ float g_hB[BDIM * HDIM];                   // hidden fp32 pong
// hidden tf32 tiled: [bm(4)][stage(16)][64 rows][36]
__device__ float g_hT3A[4 * 16 * 64 * 36];
__device__ float g_hT3B[4 * 16 * 64 * 36];
__device__ float g_enc[SDIM * BDIM * HDIM];           // elu(enc)
__device__ float g_dg[(size_t)SDIM * BDIM * 768];     // decoder gates (i,g,o)
__device__ float g_hd[SDIM * BDIM * IDIM];            // decoder hd
// grid barrier state (relative comparisons -> replay-safe)
__device__ unsigned g_bar_cnt;
__device__ volatile unsigned g_bar_gen;

__device__ __forceinline__ float sigf(float x) { return 1.0f / (1.0f + expf(-x)); }

__device__ __forceinline__ float to_tf32(float x) {
    uint32_t u;
    asm("cvt.rna.tf32.f32 %0, %1;" : "=r"(u) : "f"(x));
    return __uint_as_float(u);
}
__device__ __forceinline__ float4 cvt4(float4 v) {
    return make_float4(to_tf32(v.x), to_tf32(v.y), to_tf32(v.z), to_tf32(v.w));
}

__device__ __forceinline__ void mma8(float c[4], uint32_t a0, uint32_t a1,
                                     uint32_t a2, uint32_t a3,
                                     uint32_t b0, uint32_t b1) {
    asm volatile(
        "mma.sync.aligned.m16n8k8.row.col.f32.tf32.tf32.f32 "
        "{%0,%1,%2,%3}, {%4,%5,%6,%7}, {%8,%9}, {%0,%1,%2,%3};\n"
        : "+f"(c[0]), "+f"(c[1]), "+f"(c[2]), "+f"(c[3])
        : "r"(a0), "r"(a1), "r"(a2), "r"(a3), "r"(b0), "r"(b1));
}
__device__ __forceinline__ uint32_t fbits(float x) { return __float_as_uint(x); }
__device__ __forceinline__ uint32_t frna(float x) { return fbits(to_tf32(x)); }

__device__ __forceinline__ void cpa16(uint32_t dst, const void* src) {
    asm volatile("cp.async.cg.shared.global [%0], [%1], 16;\n" :: "r"(dst), "l"(src));
}
__device__ __forceinline__ void cpa_commit() {
    asm volatile("cp.async.commit_group;\n");
}
template <int N>
__device__ __forceinline__ void cpa_wait() {
    asm volatile("cp.async.wait_group %0;\n" :: "n"(N));
}

// ---------------- bulk-copy + mbarrier helpers --------------------------------
__device__ __forceinline__ void mbar_init(uint32_t mbar, uint32_t cnt) {
    asm volatile("mbarrier.init.shared.b64 [%0], %1;" :: "r"(mbar), "r"(cnt) : "memory");
}
__device__ __forceinline__ void mbar_expect_tx(uint32_t mbar, uint32_t bytes) {
    asm volatile("mbarrier.arrive.expect_tx.shared.b64 _, [%0], %1;"
                 :: "r"(mbar), "r"(bytes) : "memory");
}
__device__ __forceinline__ void mbar_wait(uint32_t mbar, uint32_t parity) {
    asm volatile(
        "{\n\t"
        ".reg .pred P1;\n\t"
        "WAIT_LOOP_%=:\n\t"
        "mbarrier.try_wait.parity.acquire.cta.shared::cta.b64 P1, [%0], %1, 0x989680;\n\t"
        "@P1 bra.uni WAIT_DONE_%=;\n\t"
        "bra.uni WAIT_LOOP_%=;\n\t"
        "WAIT_DONE_%=:\n\t"
        "}"
        :: "r"(mbar), "r"(parity) : "memory");
}
__device__ __forceinline__ void bulk_g2s(uint32_t dst, const void* src,
                                         uint32_t bytes, uint32_t mbar) {
    asm volatile(
        "cp.async.bulk.shared::cluster.global.mbarrier::complete_tx::bytes [%0], [%1], %2, [%3];"
        :: "r"(dst), "l"(src), "r"(bytes), "r"(mbar) : "memory");
}

// ---------------- device-wide barrier (128 CTAs, all co-resident) -------------
__device__ __forceinline__ void grid_bar() {
    __threadfence();
    __syncthreads();
    if (threadIdx.x == 0) {
        unsigned gen = g_bar_gen;
        if (atomicAdd(&g_bar_cnt, 1) == 127u) {
            g_bar_cnt = 0;
            __threadfence();
            g_bar_gen = gen + 1;
        } else {
            while (g_bar_gen == gen) { }
        }
        __threadfence();
        asm volatile("fence.proxy.async;" ::: "memory");
    }
    __syncthreads();
}

// ---------------- Whh -> tiled tf32 layout ------------------------------------
__global__ __launch_bounds__(256) void k_cvt_whh2(const float* __restrict__ W) {
    int s  = blockIdx.y;
    int bh = blockIdx.x >> 4;
    int st = blockIdx.x & 15;
    float* dst = g_Wt2 + (((size_t)s * 32 + bh) * 16 + st) * 2304;
#pragma unroll
    for (int j = 0; j < 9; j++) {
        int idx = j * 256 + threadIdx.x;   // 0..2303
        int r = idx / 36;
        int c = idx - r * 36;
        float v = 0.0f;
        if (c < 32) {
            int grow = ((r >> 4) << 9) + bh * 16 + (r & 15);  // gate*512 + hcol
            v = to_tf32(W[((size_t)s * GE + grow) * HDIM + st * 32 + c]);
        }
        dst[idx] = v;
    }
}

// ---------------- x (B,I,S) -> xT (S,B,I), tf32-rounded ----------------------
__global__ __launch_bounds__(256) void k_transpose_x(const float* __restrict__ x) {
    __shared__ float tile[32][65];
    int b  = blockIdx.x >> 3;
    int i0 = (blockIdx.x & 7) * 32;
    int tid = threadIdx.x;
    int s = tid & 63, it = tid >> 6;
#pragma unroll
    for (int j = 0; j < 8; j++) {
        int i = it * 8 + j;
        tile[i][s] = x[(b * IDIM + i0 + i) * SDIM + s];
    }
    __syncthreads();
    int i2 = tid & 31, sq = tid >> 5;
#pragma unroll
    for (int j = 0; j < 8; j++) {
        int ss = sq * 8 + j;
        g_xT[(ss * BDIM + b) * IDIM + i0 + i2] = to_tf32(tile[i2][ss]);
    }
}

__global__ void k_zero_h() {
    int i = blockIdx.x * 256 + threadIdx.x;   // grid 576*256 = 147456
    if (i < BDIM * HDIM) g_hA[i] = 0.0f;
    g_hT3A[i] = 0.0f;
}

// ---------------- Gx[s] = xT[s] @ Wih^T + biases  (CTA 128x128, warp 32x64) ---
__global__ __launch_bounds__(256) void k_gx(const float* __restrict__ Wih,
                                            const float* __restrict__ bih,
                                            const float* __restrict__ bhh) {
    __shared__ float sm[2 * 5120];
    int tid = threadIdx.x;
    int s = blockIdx.y;
    int bm = blockIdx.x & 1;
    int bn = blockIdx.x >> 1;

    const float* Ag[2]; const float* Bg[2];
    uint32_t aoff[2], boff[2];
#pragma unroll
    for (int jj = 0; jj < 2; jj++) {
        int q = tid + 256 * jj;
        int r = q >> 2, kq = q & 3;
        Ag[jj] = g_xT + (size_t)(s * BDIM + bm * 128 + r) * IDIM + kq * 4;
        Bg[jj] = Wih + ((size_t)s * GE + bn * 128 + r) * IDIM + kq * 4;
        aoff[jj] = (uint32_t)(r * 20 + kq * 4) * 4;
        boff[jj] = (uint32_t)(2560 + r * 20 + kq * 4) * 4;
    }
    uint32_t sbase = (uint32_t)__cvta_generic_to_shared(sm);

    int warp = tid >> 5, lane = tid & 31;
    int g = lane >> 2, t = lane & 3;
    int m0 = (warp >> 1) * 32, n0 = (warp & 1) * 64;

    float c[2][8][4] = {};

    cpa16(sbase + aoff[0], Ag[0]); cpa16(sbase + aoff[1], Ag[1]);
    cpa16(sbase + boff[0], Bg[0]); cpa16(sbase + boff[1], Bg[1]);
    cpa_commit();

    for (int st = 0; st < 16; st++) {
        if (st + 1 < 16) {
            uint32_t so = sbase + ((st + 1) & 1) * 5120 * 4;
            cpa16(so + aoff[0], Ag[0] + (st + 1) * 16);
            cpa16(so + aoff[1], Ag[1] + (st + 1) * 16);
            cpa16(so + boff[0], Bg[0] + (st + 1) * 16);
            cpa16(so + boff[1], Bg[1] + (st + 1) * 16);
            cpa_commit();
            cpa_wait<1>();
        } else {
            cpa_wait<0>();
        }
        __syncthreads();
        int fb = (st & 1) * 5120;
#pragma unroll
        for (int kk = 0; kk < 16; kk += 8) {
            uint32_t b0[8], b1[8];
#pragma unroll
            for (int f = 0; f < 8; f++) {
                b0[f] = frna(sm[fb + 2560 + (n0 + f * 8 + g) * 20 + kk + t]);
                b1[f] = frna(sm[fb + 2560 + (n0 + f * 8 + g) * 20 + kk + t + 4]);
            }
#pragma unroll
            for (int dm = 0; dm < 2; dm++) {
                int r0 = m0 + dm * 16 + g;
                uint32_t a0 = fbits(sm[fb + r0 * 20 + kk + t]);
                uint32_t a1 = fbits(sm[fb + (r0 + 8) * 20 + kk + t]);
                uint32_t a2 = fbits(sm[fb + r0 * 20 + kk + t + 4]);
                uint32_t a3 = fbits(sm[fb + (r0 + 8) * 20 + kk + t + 4]);
#pragma unroll
                for (int f = 0; f < 8; f++)
                    mma8(c[dm][f], a0, a1, a2, a3, b0[f], b1[f]);
            }
        }
        __syncthreads();
    }
#pragma unroll
    for (int f = 0; f < 8; f++) {
        int col = bn * 128 + n0 + f * 8 + 2 * t;
        float bi0 = bih[s * GE + col] + bhh[s * GE + col];
        float bi1 = bih[s * GE + col + 1] + bhh[s * GE + col + 1];
#pragma unroll
        for (int dm = 0; dm < 2; dm++) {
            int row = bm * 128 + m0 + dm * 16 + g;
            size_t r0 = ((size_t)s * BDIM + row) * GE + col;
            size_t r1 = ((size_t)s * BDIM + row + 8) * GE + col;
            *(float2*)&g_Gx[r0] = make_float2(c[dm][f][0] + bi0, c[dm][f][1] + bi1);
            *(float2*)&g_Gx[r1] = make_float2(c[dm][f][2] + bi0, c[dm][f][3] + bi1);
        }
    }
}

// ---------------- persistent encoder v2: cross-step B prefetch, 512 thr -------
// grid 128 = bm(4 x 64 rows) x bh(32 x [4 gates x 16 hc]); 16 warps, tile 16x16.
// Ring: 4 slots x (A 64x36 + B 64x36), mbar count=2 (A arrive + B arrive).
// B streams over gst = s*16+st, crossing step boundaries (weights are h-indep);
// A issued after grid_bar. Cs in dedicated region after the ring.
#define ESLOT 4608                 // floats per ring slot
#define ECSOFF (4 * ESLOT)         // Cs offset (floats)
#define ESMEM ((ECSOFF + 64 * 68) * 4)   // total dynamic smem bytes
__global__ __launch_bounds__(512) void k_enc_all() {
    extern __shared__ float sm[];
    __shared__ uint64_t mbar_s[4];
    int tid = threadIdx.x;
    int bm = blockIdx.x & 3;
    int bh = blockIdx.x >> 2;

    uint32_t smb = (uint32_t)__cvta_generic_to_shared(sm);
    uint32_t mb0 = (uint32_t)__cvta_generic_to_shared(mbar_s);

    if (tid == 0) {
#pragma unroll
        for (int p = 0; p < 4; p++) mbar_init(mb0 + p * 8, 2);
    }
    __syncthreads();

    int warp = tid >> 5, lane = tid & 31;
    int m0 = (warp >> 2) * 16;      // 4 m-tiles of 16
    int n0 = (warp & 3) * 16;       // 4 n-tiles of 16
    int g = lane >> 2, t = lane & 3;

    const float* Wb = g_Wt2 + (size_t)bh * 16 * 2304;   // + (s*32*16 + st)*2304

    // prologue: A stages 0..3 (step 0, from g_hT3A) + B gst 0..3
    if (tid == 0) {
        const float* Ab = g_hT3A + (size_t)bm * 16 * 2304;
#pragma unroll
        for (int p = 0; p < 4; p++) {
            uint32_t mb = mb0 + p * 8;
            mbar_expect_tx(mb, 9216);
            bulk_g2s(smb + p * ESLOT * 4, Ab + p * 2304, 9216, mb);
            mbar_expect_tx(mb, 9216);
            bulk_g2s(smb + p * ESLOT * 4 + 9216, Wb + (size_t)p * 2304, 9216, mb);
        }
    }

    for (int s = 0; s < SDIM; s++) {
        const float* hin = (s & 1) ? g_hB : g_hA;
        float* hout      = (s & 1) ? g_hA : g_hB;
        float* hT3out    = (s & 1) ? g_hT3A : g_hT3B;
        const float* Ab  = ((s & 1) ? g_hT3B : g_hT3A) + (size_t)bm * 16 * 2304;

        float c[2][4] = {};

        for (int st = 0; st < 16; st++) {
            mbar_wait(mb0 + (st & 3) * 8, (st >> 2) & 1);
            int ab = (st & 3) * ESLOT;
            int bb = ab + 2304;
#pragma unroll
            for (int kc = 0; kc < 32; kc += 8) {
                uint32_t a0 = fbits(sm[ab + (m0 + g) * 36 + kc + t]);
                uint32_t a1 = fbits(sm[ab + (m0 + g + 8) * 36 + kc + t]);
                uint32_t a2 = fbits(sm[ab + (m0 + g) * 36 + kc + t + 4]);
                uint32_t a3 = fbits(sm[ab + (m0 + g + 8) * 36 + kc + t + 4]);
#pragma unroll
                for (int f = 0; f < 2; f++) {
                    int rb = n0 + f * 8 + g;
                    uint32_t b0 = fbits(sm[bb + rb * 36 + kc + t]);
                    uint32_t b1 = fbits(sm[bb + rb * 36 + kc + t + 4]);
                    mma8(c[f], a0, a1, a2, a3, b0, b1);
                }
            }
            __syncthreads();
            if (tid == 0) {
                uint32_t mb = mb0 + (st & 3) * 8;
                if (st + 4 < 16) {               // A for this step's stage st+4
                    mbar_expect_tx(mb, 9216);
                    bulk_g2s(smb + (st & 3) * ESLOT * 4, Ab + (st + 4) * 2304, 9216, mb);
                }
                int g4 = s * 16 + st + 4;        // B streams across steps
                if (g4 < SDIM * 16) {
                    size_t boffg = ((size_t)(g4 >> 4) * 32 * 16 + (g4 & 15)) * 2304;
                    mbar_expect_tx(mb, 9216);
                    bulk_g2s(smb + (st & 3) * ESLOT * 4 + 9216, Wb + boffg, 9216, mb);
                }
            }
        }

        // accumulators -> Cs (dedicated region; no aliasing with ring)
#pragma unroll
        for (int f = 0; f < 2; f++) {
            int col0 = n0 + f * 8 + 2 * t;
            *(float2*)&sm[ECSOFF + (m0 + g) * 68 + col0]     = make_float2(c[f][0], c[f][1]);
            *(float2*)&sm[ECSOFF + (m0 + g + 8) * 68 + col0] = make_float2(c[f][2], c[f][3]);
        }
        __syncthreads();

        // fused LSTM pointwise + elu: 2 elems/thread (64 rows x 16 hcols)
        int row = tid >> 3;             // 0..63
        int hc0 = (tid & 7) * 2;        // 0..14
        int grow = bm * 64 + row;
        int gcol = bh * 16 + hc0;
        const float* Gxp = g_Gx + ((size_t)s * BDIM + grow) * GE + gcol;
        float2 gi = *(float2*)&sm[ECSOFF + row * 68 + 0 * 16 + hc0];
        float2 gf = *(float2*)&sm[ECSOFF + row * 68 + 1 * 16 + hc0];
        float2 gg = *(float2*)&sm[ECSOFF + row * 68 + 2 * 16 + hc0];
        float2 go = *(float2*)&sm[ECSOFF + row * 68 + 3 * 16 + hc0];
        float2 xi = *(const float2*)(Gxp + 0 * HDIM);
        float2 xf = *(const float2*)(Gxp + 1 * HDIM);
        float2 xg = *(const float2*)(Gxp + 2 * HDIM);
        float2 xo = *(const float2*)(Gxp + 3 * HDIM);
        float2 hp = *(const float2*)&hin[(size_t)grow * HDIM + gcol];
        float2 hv, tv, ev;
#pragma unroll
        for (int q = 0; q < 2; q++) {
            float vi = (&gi.x)[q] + (&xi.x)[q];
            float vf = (&gf.x)[q] + (&xf.x)[q];
            float vg = (&gg.x)[q] + (&xg.x)[q];
            float vo = (&go.x)[q] + (&xo.x)[q];
            float cc = sigf(vf) * (&hp.x)[q] + sigf(vi) * tanhf(vg);
            float hn = sigf(vo) * tanhf(cc);
            (&hv.x)[q] = hn;
            (&tv.x)[q] = to_tf32(hn);
            (&ev.x)[q] = hn > 0.0f ? hn : expm1f(hn);
        }
        *(float2*)&hout[(size_t)grow * HDIM + gcol] = hv;
        *(float2*)&g_enc[(size_t)s * BDIM * HDIM + (size_t)grow * HDIM + gcol] = ev;
        size_t tvo = ((size_t)(bm * 16 + (bh >> 1)) * 64 + row) * 36 + (bh & 1) * 16 + hc0;
        *(float2*)&hT3out[tvo] = tv;

        if (s < SDIM - 1) {
            grid_bar();
            if (tid == 0) {             // A for next step, stages 0..3
                const float* Ab2 = (((s + 1) & 1) ? g_hT3B : g_hT3A) + (size_t)bm * 16 * 2304;
#pragma unroll
                for (int p = 0; p < 4; p++) {
                    uint32_t mb = mb0 + p * 8;
                    mbar_expect_tx(mb, 9216);
                    bulk_g2s(smb + p * ESLOT * 4, Ab2 + p * 2304, 9216, mb);
                }
            }
        }
    }
}

// ---------------- strided residual chain --------------------------------------
__global__ void k_chain() {
    int e = blockIdx.x * 256 + threadIdx.x;
    float prev = g_enc[60 * BDIM * HDIM + e];
#pragma unroll
    for (int k = 0; k < 16; k++) {
        int off = (k * 4) * BDIM * HDIM + e;
        float v = 0.5f * g_enc[off] + 0.5f * prev;
        g_enc[off] = v;
        prev = v;
    }
}

// ---------------- decoder GEMM: enc_rev @ Wih_dec^T (i,g,o), big tiles --------
__global__ __launch_bounds__(256) void k_dec_gemm(const float* __restrict__ Wd) {
    __shared__ float sm[2 * 5120];
    int tid = threadIdx.x;
    int sd = blockIdx.y;
    int bm = blockIdx.x & 1;
    int bn = blockIdx.x >> 1;
    const int agate[3] = {0, 2, 3};
    int grow0 = agate[bn >> 1] * IDIM + (bn & 1) * 128;

    const float* Ag[2]; const float* Bg[2];
    uint32_t aoff[2], boff[2];
#pragma unroll
    for (int jj = 0; jj < 2; jj++) {
        int q = tid + 256 * jj;
        int r = q >> 2, kq = q & 3;
        Ag[jj] = g_enc + ((size_t)(63 - sd) * BDIM + bm * 128 + r) * HDIM + kq * 4;
        Bg[jj] = Wd + ((size_t)sd * GD + grow0 + r) * HDIM + kq * 4;
        aoff[jj] = (uint32_t)(r * 20 + kq * 4) * 4;
        boff[jj] = (uint32_t)(2560 + r * 20 + kq * 4) * 4;
    }
    uint32_t sbase = (uint32_t)__cvta_generic_to_shared(sm);

    int warp = tid >> 5, lane = tid & 31;
    int g = lane >> 2, t = lane & 3;
    int m0 = (warp >> 1) * 32, n0 = (warp & 1) * 64;

    float c[2][8][4] = {};

    cpa16(sbase + aoff[0], Ag[0]); cpa16(sbase + aoff[1], Ag[1]);
    cpa16(sbase + boff[0], Bg[0]); cpa16(sbase + boff[1], Bg[1]);
    cpa_commit();

    for (int st = 0; st < 32; st++) {
        if (st + 1 < 32) {
            uint32_t so = sbase + ((st + 1) & 1) * 5120 * 4;
            cpa16(so + aoff[0], Ag[0] + (st + 1) * 16);
            cpa16(so + aoff[1], Ag[1] + (st + 1) * 16);
            cpa16(so + boff[0], Bg[0] + (st + 1) * 16);
            cpa16(so + boff[1], Bg[1] + (st + 1) * 16);
            cpa_commit();
            cpa_wait<1>();
        } else {
            cpa_wait<0>();
        }
        __syncthreads();
        int fb = (st & 1) * 5120;
#pragma unroll
        for (int kk = 0; kk < 16; kk += 8) {
            uint32_t b0[8], b1[8];
#pragma unroll
            for (int f = 0; f < 8; f++) {
                b0[f] = frna(sm[fb + 2560 + (n0 + f * 8 + g) * 20 + kk + t]);
                b1[f] = frna(sm[fb + 2560 + (n0 + f * 8 + g) * 20 + kk + t + 4]);
            }
#pragma unroll
            for (int dm = 0; dm < 2; dm++) {
                int r0 = m0 + dm * 16 + g;
                uint32_t a0 = frna(sm[fb + r0 * 20 + kk + t]);
                uint32_t a1 = frna(sm[fb + (r0 + 8) * 20 + kk + t]);
                uint32_t a2 = frna(sm[fb + r0 * 20 + kk + t + 4]);
                uint32_t a3 = frna(sm[fb + (r0 + 8) * 20 + kk + t + 4]);
#pragma unroll
                for (int f = 0; f < 8; f++)
                    mma8(c[dm][f], a0, a1, a2, a3, b0[f], b1[f]);
            }
        }
        __syncthreads();
    }
#pragma unroll
    for (int f = 0; f < 8; f++) {
        int col = bn * 128 + n0 + f * 8 + 2 * t;
#pragma unroll
        for (int dm = 0; dm < 2; dm++) {
            int row = bm * 128 + m0 + dm * 16 + g;
            size_t r0 = ((size_t)sd * BDIM + row) * 768 + col;
            size_t r1 = ((size_t)sd * BDIM + row + 8) * 768 + col;
            *(float2*)&g_dg[r0] = make_float2(c[dm][f][0], c[dm][f][1]);
            *(float2*)&g_dg[r1] = make_float2(c[dm][f][2], c[dm][f][3]);
        }
    }
}

// ---------------- decoder pointwise: biases + activations ---------------------
__global__ __launch_bounds__(256) void k_dec_pw(const float* __restrict__ bid,
                                                const float* __restrict__ bhd) {
    int idx = blockIdx.x * 256 + threadIdx.x;
    int icg = idx & 63;
    int row = (idx >> 6) & 255;
    int sd  = idx >> 14;
    int ic  = icg * 4;
    size_t base = ((size_t)sd * BDIM + row) * 768;
    float4 vi = *(const float4*)&g_dg[base + 0 * IDIM + ic];
    float4 vg = *(const float4*)&g_dg[base + 1 * IDIM + ic];
    float4 vo = *(const float4*)&g_dg[base + 2 * IDIM + ic];
    const float* B1 = bid + sd * GD;
    const float* B2 = bhd + sd * GD;
    float4 bi1 = *(const float4*)&B1[0 * IDIM + ic];
    float4 bi2 = *(const float4*)&B2[0 * IDIM + ic];
    float4 bg1 = *(const float4*)&B1[2 * IDIM + ic];
    float4 bg2 = *(const float4*)&B2[2 * IDIM + ic];
    float4 bo1 = *(const float4*)&B1[3 * IDIM + ic];
    float4 bo2 = *(const float4*)&B2[3 * IDIM + ic];
    float4 ov;
#pragma unroll
    for (int q = 0; q < 4; q++) {
        float gi = (&vi.x)[q] + (&bi1.x)[q] + (&bi2.x)[q];
        float gg = (&vg.x)[q] + (&bg1.x)[q] + (&bg2.x)[q];
        float go = (&vo.x)[q] + (&bo1.x)[q] + (&bo2.x)[q];
        float cc = sigf(gi) * tanhf(gg);
        (&ov.x)[q] = sigf(go) * tanhf(cc);
    }
    *(float4*)&g_hd[((size_t)sd * BDIM + row) * IDIM + ic] = ov;
}

// ---------------- cumsum(4) + tanh + reverse + transpose to (B,I,S) -----------
__global__ void k_final(float* __restrict__ out) {
    int idx = blockIdx.x * 256 + threadIdx.x;
    int i = idx & 255;
    int q = (idx >> 8) & 15;
    int b = idx >> 12;
    int base = (4 * q * BDIM + b) * IDIM + i;
    float a0 = g_hd[base];
    float a1 = g_hd[base + 1 * BDIM * IDIM];
    float a2 = g_hd[base + 2 * BDIM * IDIM];
    float a3 = g_hd[base + 3 * BDIM * IDIM];
    float r0 = a0, r1 = r0 + a1, r2 = r1 + a2, r3 = r2 + a3;
    float4 v = make_float4(tanhf(r3), tanhf(r2), tanhf(r1), tanhf(r0));
    *(float4*)(out + (size_t)(b * IDIM + i) * SDIM + (60 - 4 * q)) = v;
}

// ---------------- launch ------------------------------------------------------
extern "C" void kernel_launch(void* const* d_in, const int* in_sizes, int n_in,
                              void* d_out, int out_size) {
    const float* x       = (const float*)d_in[0];
    const float* Wih_enc = (const float*)d_in[1];
    const float* Whh_enc = (const float*)d_in[2];
    const float* bih_enc = (const float*)d_in[3];
    const float* bhh_enc = (const float*)d_in[4];
    const float* Wih_dec = (const float*)d_in[5];
    // d_in[6] = Whh_dec: unused by the reference computation
    const float* bih_dec = (const float*)d_in[7];
    const float* bhh_dec = (const float*)d_in[8];
    float* out = (float*)d_out;

    cudaFuncSetAttribute(k_enc_all, cudaFuncAttributeMaxDynamicSharedMemorySize, ESMEM);

    k_cvt_whh2<<<dim3(512, 64), 256>>>(Whh_enc);
    k_transpose_x<<<2048, 256>>>(x);
    k_zero_h<<<576, 256>>>();
    k_gx<<<dim3(32, 64), 256>>>(Wih_enc, bih_enc, bhh_enc);
    k_enc_all<<<128, 512, ESMEM>>>();
    k_chain<<<512, 256>>>();
    k_dec_gemm<<<dim3(12, 64), 256>>>(Wih_dec);
    k_dec_pw<<<4096, 256>>>(bih_dec, bhh_dec);
    k_final<<<4096, 256>>>(out);
}

// round 16
// speedup vs baseline: 1.0519x; 1.0228x over previous
#include <cuda_runtime.h>
#include <math.h>
#include <stdint.h>

#define BDIM 256
#define IDIM 256
#define HDIM 512
#define SDIM 64
#define GE 2048   // 4*H
#define GD 1024   // 4*I

// ---------------- scratch (device globals: allocation-free contract) ----------
__device__ float g_xT[SDIM * BDIM * IDIM];            // x transposed (S,B,I), tf32-rounded
__device__ float g_Gx[(size_t)SDIM * BDIM * GE];      // x@Wih^T + biases (fp32)
// Whh tiled+rounded: [s][bh(32)][stage(16)][64 rows (gate*16+hc)][36 (32 K + 4 pad)]
__device__ float g_Wt2[(size_t)SDIM * 32 * 16 * 64 * 36];
__device__ float g_hA[BDIM * HDIM];                   // hidden fp32 ping
__device__ float g_hB[BDIM * HDIM];                   // hidden fp32 pong
// hidden tf32 tiled: [bm(4)][stage(16)][64 rows][36]
__device__ float g_hT3A[4 * 16 * 64 * 36];
__device__ float g_hT3B[4 * 16 * 64 * 36];
__device__ float g_enc[SDIM * BDIM * HDIM];           // elu(enc)
__device__ float g_dg[(size_t)SDIM * BDIM * 768];     // decoder gates (i,g,o)
__device__ float g_hd[SDIM * BDIM * IDIM];            // decoder hd

__device__ __forceinline__ float sigf(float x) { return 1.0f / (1.0f + expf(-x)); }

__device__ __forceinline__ float to_tf32(float x) {
    uint32_t u;
    asm("cvt.rna.tf32.f32 %0, %1;" : "=r"(u) : "f"(x));
    return __uint_as_float(u);
}
__device__ __forceinline__ float4 cvt4(float4 v) {
    return make_float4(to_tf32(v.x), to_tf32(v.y), to_tf32(v.z), to_tf32(v.w));
}

__device__ __forceinline__ void mma8(float c[4], uint32_t a0, uint32_t a1,
                                     uint32_t a2, uint32_t a3,
                                     uint32_t b0, uint32_t b1) {
    asm volatile(
        "mma.sync.aligned.m16n8k8.row.col.f32.tf32.tf32.f32 "
        "{%0,%1,%2,%3}, {%4,%5,%6,%7}, {%8,%9}, {%0,%1,%2,%3};\n"
        : "+f"(c[0]), "+f"(c[1]), "+f"(c[2]), "+f"(c[3])
        : "r"(a0), "r"(a1), "r"(a2), "r"(a3), "r"(b0), "r"(b1));
}
__device__ __forceinline__ uint32_t fbits(float x) { return __float_as_uint(x); }
__device__ __forceinline__ uint32_t frna(float x) { return fbits(to_tf32(x)); }

__device__ __forceinline__ void cpa16(uint32_t dst, const void* src) {
    asm volatile("cp.async.cg.shared.global [%0], [%1], 16;\n" :: "r"(dst), "l"(src));
}
__device__ __forceinline__ void cpa_commit() {
    asm volatile("cp.async.commit_group;\n");
}
template <int N>
__device__ __forceinline__ void cpa_wait() {
    asm volatile("cp.async.wait_group %0;\n" :: "n"(N));
}

// ---------------- bulk-copy + mbarrier helpers --------------------------------
__device__ __forceinline__ void mbar_init(uint32_t mbar, uint32_t cnt) {
    asm volatile("mbarrier.init.shared.b64 [%0], %1;" :: "r"(mbar), "r"(cnt) : "memory");
}
__device__ __forceinline__ void mbar_expect_tx(uint32_t mbar, uint32_t bytes) {
    asm volatile("mbarrier.arrive.expect_tx.shared.b64 _, [%0], %1;"
                 :: "r"(mbar), "r"(bytes) : "memory");
}
__device__ __forceinline__ void mbar_wait(uint32_t mbar, uint32_t parity) {
    asm volatile(
        "{\n\t"
        ".reg .pred P1;\n\t"
        "WAIT_LOOP_%=:\n\t"
        "mbarrier.try_wait.parity.acquire.cta.shared::cta.b64 P1, [%0], %1, 0x989680;\n\t"
        "@P1 bra.uni WAIT_DONE_%=;\n\t"
        "bra.uni WAIT_LOOP_%=;\n\t"
        "WAIT_DONE_%=:\n\t"
        "}"
        :: "r"(mbar), "r"(parity) : "memory");
}
__device__ __forceinline__ void bulk_g2s(uint32_t dst, const void* src,
                                         uint32_t bytes, uint32_t mbar) {
    asm volatile(
        "cp.async.bulk.shared::cluster.global.mbarrier::complete_tx::bytes [%0], [%1], %2, [%3];"
        :: "r"(dst), "l"(src), "r"(bytes), "r"(mbar) : "memory");
}

// ---------------- x (B,I,S) -> xT (S,B,I), tf32-rounded ----------------------
__global__ __launch_bounds__(256) void k_transpose_x(const float* __restrict__ x) {
    __shared__ float tile[32][65];
    int b  = blockIdx.x >> 3;
    int i0 = (blockIdx.x & 7) * 32;
    int tid = threadIdx.x;
    int s = tid & 63, it = tid >> 6;
#pragma unroll
    for (int j = 0; j < 8; j++) {
        int i = it * 8 + j;
        tile[i][s] = x[(b * IDIM + i0 + i) * SDIM + s];
    }
    __syncthreads();
    int i2 = tid & 31, sq = tid >> 5;
#pragma unroll
    for (int j = 0; j < 8; j++) {
        int ss = sq * 8 + j;
        g_xT[(ss * BDIM + b) * IDIM + i0 + i2] = to_tf32(tile[i2][ss]);
    }
}

__global__ void k_zero_h() {
    int i = blockIdx.x * 256 + threadIdx.x;   // grid 576*256 = 147456
    if (i < BDIM * HDIM) g_hA[i] = 0.0f;
    g_hT3A[i] = 0.0f;
}

// ---------------- Gx[s] = xT[s] @ Wih^T + biases + fused Whh cvt --------------
// grid (32, 64): bm = x&1, bn = x>>1. K=256, 16 stages of 16, cp.async 2-stage.
// After the GEMM epilogue, each CTA converts a disjoint 64-row x 512-col slab
// of Whh_enc[s] into the tiled tf32 layout g_Wt2 (replaces k_cvt_whh2).
__global__ __launch_bounds__(256) void k_gx(const float* __restrict__ Wih,
                                            const float* __restrict__ Whh,
                                            const float* __restrict__ bih,
                                            const float* __restrict__ bhh) {
    __shared__ float sm[2 * 5120];
    int tid = threadIdx.x;
    int s = blockIdx.y;
    int bm = blockIdx.x & 1;
    int bn = blockIdx.x >> 1;

    const float* Ag[2]; const float* Bg[2];
    uint32_t aoff[2], boff[2];
#pragma unroll
    for (int jj = 0; jj < 2; jj++) {
        int q = tid + 256 * jj;
        int r = q >> 2, kq = q & 3;
        Ag[jj] = g_xT + (size_t)(s * BDIM + bm * 128 + r) * IDIM + kq * 4;
        Bg[jj] = Wih + ((size_t)s * GE + bn * 128 + r) * IDIM + kq * 4;
        aoff[jj] = (uint32_t)(r * 20 + kq * 4) * 4;
        boff[jj] = (uint32_t)(2560 + r * 20 + kq * 4) * 4;
    }
    uint32_t sbase = (uint32_t)__cvta_generic_to_shared(sm);

    int warp = tid >> 5, lane = tid & 31;
    int g = lane >> 2, t = lane & 3;
    int m0 = (warp >> 1) * 32, n0 = (warp & 1) * 64;

    float c[2][8][4] = {};

    cpa16(sbase + aoff[0], Ag[0]); cpa16(sbase + aoff[1], Ag[1]);
    cpa16(sbase + boff[0], Bg[0]); cpa16(sbase + boff[1], Bg[1]);
    cpa_commit();

    for (int st = 0; st < 16; st++) {
        if (st + 1 < 16) {
            uint32_t so = sbase + ((st + 1) & 1) * 5120 * 4;
            cpa16(so + aoff[0], Ag[0] + (st + 1) * 16);
            cpa16(so + aoff[1], Ag[1] + (st + 1) * 16);
            cpa16(so + boff[0], Bg[0] + (st + 1) * 16);
            cpa16(so + boff[1], Bg[1] + (st + 1) * 16);
            cpa_commit();
            cpa_wait<1>();
        } else {
            cpa_wait<0>();
        }
        __syncthreads();
        int fb = (st & 1) * 5120;
#pragma unroll
        for (int kk = 0; kk < 16; kk += 8) {
            uint32_t b0[8], b1[8];
#pragma unroll
            for (int f = 0; f < 8; f++) {
                b0[f] = frna(sm[fb + 2560 + (n0 + f * 8 + g) * 20 + kk + t]);
                b1[f] = frna(sm[fb + 2560 + (n0 + f * 8 + g) * 20 + kk + t + 4]);
            }
#pragma unroll
            for (int dm = 0; dm < 2; dm++) {
                int r0 = m0 + dm * 16 + g;
                uint32_t a0 = fbits(sm[fb + r0 * 20 + kk + t]);
                uint32_t a1 = fbits(sm[fb + (r0 + 8) * 20 + kk + t]);
                uint32_t a2 = fbits(sm[fb + r0 * 20 + kk + t + 4]);
                uint32_t a3 = fbits(sm[fb + (r0 + 8) * 20 + kk + t + 4]);
#pragma unroll
                for (int f = 0; f < 8; f++)
                    mma8(c[dm][f], a0, a1, a2, a3, b0[f], b1[f]);
            }
        }
        __syncthreads();
    }
#pragma unroll
    for (int f = 0; f < 8; f++) {
        int col = bn * 128 + n0 + f * 8 + 2 * t;
        float bi0 = bih[s * GE + col] + bhh[s * GE + col];
        float bi1 = bih[s * GE + col + 1] + bhh[s * GE + col + 1];
#pragma unroll
        for (int dm = 0; dm < 2; dm++) {
            int row = bm * 128 + m0 + dm * 16 + g;
            size_t r0 = ((size_t)s * BDIM + row) * GE + col;
            size_t r1 = ((size_t)s * BDIM + row + 8) * GE + col;
            *(float2*)&g_Gx[r0] = make_float2(c[dm][f][0] + bi0, c[dm][f][1] + bi1);
            *(float2*)&g_Gx[r1] = make_float2(c[dm][f][2] + bi0, c[dm][f][3] + bi1);
        }
    }

    // ---- fused Whh -> g_Wt2 tiled tf32 conversion (64 rows x 512 cols) ----
    {
        int chunk = bm * 16 + bn;                 // 0..31, rows [chunk*64, +64)
        const float* Ws = Whh + (size_t)s * GE * HDIM;
        float* Dt = g_Wt2 + (size_t)s * 32 * 16 * 2304;
#pragma unroll 4
        for (int j = 0; j < 32; j++) {
            int fid = j * 256 + tid;              // float4 id over 64x128
            int r   = fid >> 7;                   // 0..63
            int c4  = fid & 127;
            int gr  = chunk * 64 + r;             // raw gate-row 0..2047
            int col0 = c4 * 4;
            float4 v = *(const float4*)&Ws[(size_t)gr * HDIM + col0];
            int gate = gr >> 9;
            int hcol = gr & 511;
            int bh = hcol >> 4;
            int r16 = hcol & 15;
            int stg = col0 >> 5;
            int cc  = col0 & 31;
            size_t di = ((size_t)bh * 16 + stg) * 2304 + (gate * 16 + r16) * 36 + cc;
            *(float4*)&Dt[di] = cvt4(v);
        }
    }
}

// ---------------- encoder step (R10): bulk-copy ring, 128 CTAs of 64x64 -------
// grid 128 = bm(4 x 64 rows) x bh(32 x [4 gates x 16 hc]). K=512 -> 16 stages
// of K=32. Per stage: A tile 64x36 (9216B) + B tile 64x36 (9216B), each ONE
// cp.async.bulk into a 4-slot mbarrier ring. Warp tile 32x16 (2x4 warps).
#define ESLOT 4608   // floats per ring slot (A 2304 + B 2304)
__global__ __launch_bounds__(256) void k_enc_step(int s) {
    extern __shared__ float sm[];
    __shared__ uint64_t mbar_s[4];
    int tid = threadIdx.x;
    int bm = blockIdx.x & 3;
    int bh = blockIdx.x >> 2;

    const float* hT3in = (s & 1) ? g_hT3B : g_hT3A;
    float* hT3out      = (s & 1) ? g_hT3A : g_hT3B;
    const float* hin   = (s & 1) ? g_hB : g_hA;
    float* hout        = (s & 1) ? g_hA : g_hB;

    const float* Abase = hT3in + (size_t)bm * 16 * 2304;               // [st][64][36]
    const float* Bbase = g_Wt2 + (((size_t)s * 32 + bh) * 16) * 2304;  // [st][64][36]

    uint32_t smb = (uint32_t)__cvta_generic_to_shared(sm);
    uint32_t mb0 = (uint32_t)__cvta_generic_to_shared(mbar_s);

    if (tid == 0) {
#pragma unroll
        for (int p = 0; p < 4; p++) mbar_init(mb0 + p * 8, 1);
    }
    __syncthreads();
    if (tid == 0) {
#pragma unroll
        for (int p = 0; p < 4; p++) {
            uint32_t mb = mb0 + p * 8;
            mbar_expect_tx(mb, 18432);
            bulk_g2s(smb + p * ESLOT * 4,        Abase + p * 2304, 9216, mb);
            bulk_g2s(smb + p * ESLOT * 4 + 9216, Bbase + p * 2304, 9216, mb);
        }
    }

    int warp = tid >> 5, lane = tid & 31;
    int m0 = (warp >> 2) * 32;          // 2 m-tiles of 32
    int n0 = (warp & 3) * 16;           // 4 n-tiles of 16
    int g = lane >> 2, t = lane & 3;

    float c[2][2][4] = {};

    for (int st = 0; st < 16; st++) {
        mbar_wait(mb0 + (st & 3) * 8, (st >> 2) & 1);
        int ab = (st & 3) * ESLOT;
        int bb = ab + 2304;
#pragma unroll
        for (int kc = 0; kc < 32; kc += 8) {
            uint32_t b0[2], b1[2];
#pragma unroll
            for (int f = 0; f < 2; f++) {
                int rb = n0 + f * 8 + g;
                b0[f] = fbits(sm[bb + rb * 36 + kc + t]);
                b1[f] = fbits(sm[bb + rb * 36 + kc + t + 4]);
            }
#pragma unroll
            for (int dm = 0; dm < 2; dm++) {
                int r0 = m0 + dm * 16 + g;
                uint32_t a0 = fbits(sm[ab + r0 * 36 + kc + t]);
                uint32_t a1 = fbits(sm[ab + (r0 + 8) * 36 + kc + t]);
                uint32_t a2 = fbits(sm[ab + r0 * 36 + kc + t + 4]);
                uint32_t a3 = fbits(sm[ab + (r0 + 8) * 36 + kc + t + 4]);
#pragma unroll
                for (int f = 0; f < 2; f++)
                    mma8(c[dm][f], a0, a1, a2, a3, b0[f], b1[f]);
            }
        }
        __syncthreads();
        if (tid == 0 && st + 4 < 16) {
            uint32_t mb = mb0 + (st & 3) * 8;
            mbar_expect_tx(mb, 18432);
            bulk_g2s(smb + (st & 3) * ESLOT * 4,        Abase + (st + 4) * 2304, 9216, mb);
            bulk_g2s(smb + (st & 3) * ESLOT * 4 + 9216, Bbase + (st + 4) * 2304, 9216, mb);
        }
    }

    // accumulators -> Cs (64 x 68; aliases ring slots, free after final barrier)
#pragma unroll
    for (int dm = 0; dm < 2; dm++)
#pragma unroll
    for (int f = 0; f < 2; f++) {
        int col0 = n0 + f * 8 + 2 * t;
        *(float2*)&sm[(m0 + dm * 16 + g) * 68 + col0]     = make_float2(c[dm][f][0], c[dm][f][1]);
        *(float2*)&sm[(m0 + dm * 16 + g + 8) * 68 + col0] = make_float2(c[dm][f][2], c[dm][f][3]);
    }
    __syncthreads();

    // fused LSTM pointwise + elu: 4 elems/thread (64 rows x 16 hcols)
    int row = tid >> 2;             // 0..63
    int hc0 = (tid & 3) * 4;        // 0,4,8,12
    int grow = bm * 64 + row;
    int gcol = bh * 16 + hc0;
    const float* Gxp = g_Gx + ((size_t)s * BDIM + grow) * GE + gcol;
    float4 gi = *(float4*)&sm[row * 68 + 0 * 16 + hc0];
    float4 gf = *(float4*)&sm[row * 68 + 1 * 16 + hc0];
    float4 gg = *(float4*)&sm[row * 68 + 2 * 16 + hc0];
    float4 go = *(float4*)&sm[row * 68 + 3 * 16 + hc0];
    float4 xi = *(const float4*)(Gxp + 0 * HDIM);
    float4 xf = *(const float4*)(Gxp + 1 * HDIM);
    float4 xg = *(const float4*)(Gxp + 2 * HDIM);
    float4 xo = *(const float4*)(Gxp + 3 * HDIM);
    float4 hp = *(const float4*)&hin[(size_t)grow * HDIM + gcol];
    float4 hv, tv, ev;
#pragma unroll
    for (int q = 0; q < 4; q++) {
        float vi = (&gi.x)[q] + (&xi.x)[q];
        float vf = (&gf.x)[q] + (&xf.x)[q];
        float vg = (&gg.x)[q] + (&xg.x)[q];
        float vo = (&go.x)[q] + (&xo.x)[q];
        float cc = sigf(vf) * (&hp.x)[q] + sigf(vi) * tanhf(vg);
        float hn = sigf(vo) * tanhf(cc);
        (&hv.x)[q] = hn;
        (&tv.x)[q] = to_tf32(hn);
        (&ev.x)[q] = hn > 0.0f ? hn : expm1f(hn);
    }
    *(float4*)&hout[(size_t)grow * HDIM + gcol] = hv;
    *(float4*)&g_enc[(size_t)s * BDIM * HDIM + (size_t)grow * HDIM + gcol] = ev;
    // tiled tf32 h for next step's A bulks: [bm][stage][row][36]
    size_t tvo = ((size_t)(bm * 16 + (bh >> 1)) * 64 + row) * 36 + (bh & 1) * 16 + hc0;
    *(float4*)&hT3out[tvo] = tv;
}

// ---------------- strided residual chain --------------------------------------
__global__ void k_chain() {
    int e = blockIdx.x * 256 + threadIdx.x;
    float prev = g_enc[60 * BDIM * HDIM + e];
#pragma unroll
    for (int k = 0; k < 16; k++) {
        int off = (k * 4) * BDIM * HDIM + e;
        float v = 0.5f * g_enc[off] + 0.5f * prev;
        g_enc[off] = v;
        prev = v;
    }
}

// ---------------- decoder GEMM: enc_rev @ Wih_dec^T (i,g,o), big tiles --------
__global__ __launch_bounds__(256) void k_dec_gemm(const float* __restrict__ Wd) {
    __shared__ float sm[2 * 5120];
    int tid = threadIdx.x;
    int sd = blockIdx.y;
    int bm = blockIdx.x & 1;
    int bn = blockIdx.x >> 1;
    const int agate[3] = {0, 2, 3};
    int grow0 = agate[bn >> 1] * IDIM + (bn & 1) * 128;

    const float* Ag[2]; const float* Bg[2];
    uint32_t aoff[2], boff[2];
#pragma unroll
    for (int jj = 0; jj < 2; jj++) {
        int q = tid + 256 * jj;
        int r = q >> 2, kq = q & 3;
        Ag[jj] = g_enc + ((size_t)(63 - sd) * BDIM + bm * 128 + r) * HDIM + kq * 4;
        Bg[jj] = Wd + ((size_t)sd * GD + grow0 + r) * HDIM + kq * 4;
        aoff[jj] = (uint32_t)(r * 20 + kq * 4) * 4;
        boff[jj] = (uint32_t)(2560 + r * 20 + kq * 4) * 4;
    }
    uint32_t sbase = (uint32_t)__cvta_generic_to_shared(sm);

    int warp = tid >> 5, lane = tid & 31;
    int g = lane >> 2, t = lane & 3;
    int m0 = (warp >> 1) * 32, n0 = (warp & 1) * 64;

    float c[2][8][4] = {};

    cpa16(sbase + aoff[0], Ag[0]); cpa16(sbase + aoff[1], Ag[1]);
    cpa16(sbase + boff[0], Bg[0]); cpa16(sbase + boff[1], Bg[1]);
    cpa_commit();

    for (int st = 0; st < 32; st++) {
        if (st + 1 < 32) {
            uint32_t so = sbase + ((st + 1) & 1) * 5120 * 4;
            cpa16(so + aoff[0], Ag[0] + (st + 1) * 16);
            cpa16(so + aoff[1], Ag[1] + (st + 1) * 16);
            cpa16(so + boff[0], Bg[0] + (st + 1) * 16);
            cpa16(so + boff[1], Bg[1] + (st + 1) * 16);
            cpa_commit();
            cpa_wait<1>();
        } else {
            cpa_wait<0>();
        }
        __syncthreads();
        int fb = (st & 1) * 5120;
#pragma unroll
        for (int kk = 0; kk < 16; kk += 8) {
            uint32_t b0[8], b1[8];
#pragma unroll
            for (int f = 0; f < 8; f++) {
                b0[f] = frna(sm[fb + 2560 + (n0 + f * 8 + g) * 20 + kk + t]);
                b1[f] = frna(sm[fb + 2560 + (n0 + f * 8 + g) * 20 + kk + t + 4]);
            }
#pragma unroll
            for (int dm = 0; dm < 2; dm++) {
                int r0 = m0 + dm * 16 + g;
                uint32_t a0 = frna(sm[fb + r0 * 20 + kk + t]);
                uint32_t a1 = frna(sm[fb + (r0 + 8) * 20 + kk + t]);
                uint32_t a2 = frna(sm[fb + r0 * 20 + kk + t + 4]);
                uint32_t a3 = frna(sm[fb + (r0 + 8) * 20 + kk + t + 4]);
#pragma unroll
                for (int f = 0; f < 8; f++)
                    mma8(c[dm][f], a0, a1, a2, a3, b0[f], b1[f]);
            }
        }
        __syncthreads();
    }
#pragma unroll
    for (int f = 0; f < 8; f++) {
        int col = bn * 128 + n0 + f * 8 + 2 * t;
#pragma unroll
        for (int dm = 0; dm < 2; dm++) {
            int row = bm * 128 + m0 + dm * 16 + g;
            size_t r0 = ((size_t)sd * BDIM + row) * 768 + col;
            size_t r1 = ((size_t)sd * BDIM + row + 8) * 768 + col;
            *(float2*)&g_dg[r0] = make_float2(c[dm][f][0], c[dm][f][1]);
            *(float2*)&g_dg[r1] = make_float2(c[dm][f][2], c[dm][f][3]);
        }
    }
}

// ---------------- decoder pointwise: biases + activations ---------------------
__global__ __launch_bounds__(256) void k_dec_pw(const float* __restrict__ bid,
                                                const float* __restrict__ bhd) {
    int idx = blockIdx.x * 256 + threadIdx.x;
    int icg = idx & 63;
    int row = (idx >> 6) & 255;
    int sd  = idx >> 14;
    int ic  = icg * 4;
    size_t base = ((size_t)sd * BDIM + row) * 768;
    float4 vi = *(const float4*)&g_dg[base + 0 * IDIM + ic];
    float4 vg = *(const float4*)&g_dg[base + 1 * IDIM + ic];
    float4 vo = *(const float4*)&g_dg[base + 2 * IDIM + ic];
    const float* B1 = bid + sd * GD;
    const float* B2 = bhd + sd * GD;
    float4 bi1 = *(const float4*)&B1[0 * IDIM + ic];
    float4 bi2 = *(const float4*)&B2[0 * IDIM + ic];
    float4 bg1 = *(const float4*)&B1[2 * IDIM + ic];
    float4 bg2 = *(const float4*)&B2[2 * IDIM + ic];
    float4 bo1 = *(const float4*)&B1[3 * IDIM + ic];
    float4 bo2 = *(const float4*)&B2[3 * IDIM + ic];
    float4 ov;
#pragma unroll
    for (int q = 0; q < 4; q++) {
        float gi = (&vi.x)[q] + (&bi1.x)[q] + (&bi2.x)[q];
        float gg = (&vg.x)[q] + (&bg1.x)[q] + (&bg2.x)[q];
        float go = (&vo.x)[q] + (&bo1.x)[q] + (&bo2.x)[q];
        float cc = sigf(gi) * tanhf(gg);
        (&ov.x)[q] = sigf(go) * tanhf(cc);
    }
    *(float4*)&g_hd[((size_t)sd * BDIM + row) * IDIM + ic] = ov;
}

// ---------------- cumsum(4) + tanh + reverse + transpose to (B,I,S) -----------
__global__ void k_final(float* __restrict__ out) {
    int idx = blockIdx.x * 256 + threadIdx.x;
    int i = idx & 255;
    int q = (idx >> 8) & 15;
    int b = idx >> 12;
    int base = (4 * q * BDIM + b) * IDIM + i;
    float a0 = g_hd[base];
    float a1 = g_hd[base + 1 * BDIM * IDIM];
    float a2 = g_hd[base + 2 * BDIM * IDIM];
    float a3 = g_hd[base + 3 * BDIM * IDIM];
    float r0 = a0, r1 = r0 + a1, r2 = r1 + a2, r3 = r2 + a3;
    float4 v = make_float4(tanhf(r3), tanhf(r2), tanhf(r1), tanhf(r0));
    *(float4*)(out + (size_t)(b * IDIM + i) * SDIM + (60 - 4 * q)) = v;
}

// ---------------- launch ------------------------------------------------------
extern "C" void kernel_launch(void* const* d_in, const int* in_sizes, int n_in,
                              void* d_out, int out_size) {
    const float* x       = (const float*)d_in[0];
    const float* Wih_enc = (const float*)d_in[1];
    const float* Whh_enc = (const float*)d_in[2];
    const float* bih_enc = (const float*)d_in[3];
    const float* bhh_enc = (const float*)d_in[4];
    const float* Wih_dec = (const float*)d_in[5];
    // d_in[6] = Whh_dec: unused by the reference computation
    const float* bih_dec = (const float*)d_in[7];
    const float* bhh_dec = (const float*)d_in[8];
    float* out = (float*)d_out;

    cudaFuncSetAttribute(k_enc_step, cudaFuncAttributeMaxDynamicSharedMemorySize,
                         4 * ESLOT * 4);

    k_transpose_x<<<2048, 256>>>(x);
    k_zero_h<<<576, 256>>>();
    k_gx<<<dim3(32, 64), 256>>>(Wih_enc, Whh_enc, bih_enc, bhh_enc);
    for (int s = 0; s < SDIM; s++) {
        k_enc_step<<<128, 256, 4 * ESLOT * 4>>>(s);
    }
    k_chain<<<512, 256>>>();
    k_dec_gemm<<<dim3(12, 64), 256>>>(Wih_dec);
    k_dec_pw<<<4096, 256>>>(bih_dec, bhh_dec);
    k_final<<<4096, 256>>>(out);
}

// round 17
// speedup vs baseline: 1.1180x; 1.0628x over previous
#include <cuda_runtime.h>
#include <math.h>
#include <stdint.h>

#define BDIM 256
#define IDIM 256
#define HDIM 512
#define SDIM 64
#define GE 2048   // 4*H
#define GD 1024   // 4*I

// ---------------- scratch (device globals: allocation-free contract) ----------
__device__ float g_xT[SDIM * BDIM * IDIM];            // x transposed (S,B,I), tf32-rounded
__device__ float g_Gx[(size_t)SDIM * BDIM * GE];      // x@Wih^T + biases (fp32)
// Whh tiled+rounded: [s][bh(32)][stage(16)][64 rows (gate*16+hc)][36 (32 K + 4 pad)]
__device__ float g_Wt2[(size_t)SDIM * 32 * 16 * 64 * 36];
__device__ float g_hA[BDIM * HDIM];                   // hidden fp32 ping
__device__ float g_hB[BDIM * HDIM];                   // hidden fp32 pong
// hidden tf32 tiled: [bm(8)][stage(16)][32 rows][36]
__device__ float g_hT3A[8 * 16 * 32 * 36];
__device__ float g_hT3B[8 * 16 * 32 * 36];
__device__ float g_enc[SDIM * BDIM * HDIM];           // elu(enc)
__device__ float g_dg[(size_t)SDIM * BDIM * 768];     // decoder gates (i,g,o)
__device__ float g_hd[SDIM * BDIM * IDIM];            // decoder hd

__device__ __forceinline__ float sigf(float x) { return 1.0f / (1.0f + expf(-x)); }

__device__ __forceinline__ float to_tf32(float x) {
    uint32_t u;
    asm("cvt.rna.tf32.f32 %0, %1;" : "=r"(u) : "f"(x));
    return __uint_as_float(u);
}
__device__ __forceinline__ float4 cvt4(float4 v) {
    return make_float4(to_tf32(v.x), to_tf32(v.y), to_tf32(v.z), to_tf32(v.w));
}

__device__ __forceinline__ void mma8(float c[4], uint32_t a0, uint32_t a1,
                                     uint32_t a2, uint32_t a3,
                                     uint32_t b0, uint32_t b1) {
    asm volatile(
        "mma.sync.aligned.m16n8k8.row.col.f32.tf32.tf32.f32 "
        "{%0,%1,%2,%3}, {%4,%5,%6,%7}, {%8,%9}, {%0,%1,%2,%3};\n"
        : "+f"(c[0]), "+f"(c[1]), "+f"(c[2]), "+f"(c[3])
        : "r"(a0), "r"(a1), "r"(a2), "r"(a3), "r"(b0), "r"(b1));
}
__device__ __forceinline__ uint32_t fbits(float x) { return __float_as_uint(x); }
__device__ __forceinline__ uint32_t frna(float x) { return fbits(to_tf32(x)); }

__device__ __forceinline__ void cpa16(uint32_t dst, const void* src) {
    asm volatile("cp.async.cg.shared.global [%0], [%1], 16;\n" :: "r"(dst), "l"(src));
}
__device__ __forceinline__ void cpa_commit() {
    asm volatile("cp.async.commit_group;\n");
}
template <int N>
__device__ __forceinline__ void cpa_wait() {
    asm volatile("cp.async.wait_group %0;\n" :: "n"(N));
}

// ---------------- bulk-copy + mbarrier helpers --------------------------------
__device__ __forceinline__ void mbar_init(uint32_t mbar, uint32_t cnt) {
    asm volatile("mbarrier.init.shared.b64 [%0], %1;" :: "r"(mbar), "r"(cnt) : "memory");
}
__device__ __forceinline__ void mbar_expect_tx(uint32_t mbar, uint32_t bytes) {
    asm volatile("mbarrier.arrive.expect_tx.shared.b64 _, [%0], %1;"
                 :: "r"(mbar), "r"(bytes) : "memory");
}
__device__ __forceinline__ void mbar_wait(uint32_t mbar, uint32_t parity) {
    asm volatile(
        "{\n\t"
        ".reg .pred P1;\n\t"
        "WAIT_LOOP_%=:\n\t"
        "mbarrier.try_wait.parity.acquire.cta.shared::cta.b64 P1, [%0], %1, 0x989680;\n\t"
        "@P1 bra.uni WAIT_DONE_%=;\n\t"
        "bra.uni WAIT_LOOP_%=;\n\t"
        "WAIT_DONE_%=:\n\t"
        "}"
        :: "r"(mbar), "r"(parity) : "memory");
}
__device__ __forceinline__ void bulk_g2s(uint32_t dst, const void* src,
                                         uint32_t bytes, uint32_t mbar) {
    asm volatile(
        "cp.async.bulk.shared::cluster.global.mbarrier::complete_tx::bytes [%0], [%1], %2, [%3];"
        :: "r"(dst), "l"(src), "r"(bytes), "r"(mbar) : "memory");
}

// ---------------- x (B,I,S) -> xT (S,B,I), tf32-rounded ----------------------
__global__ __launch_bounds__(256) void k_transpose_x(const float* __restrict__ x) {
    __shared__ float tile[32][65];
    int b  = blockIdx.x >> 3;
    int i0 = (blockIdx.x & 7) * 32;
    int tid = threadIdx.x;
    int s = tid & 63, it = tid >> 6;
#pragma unroll
    for (int j = 0; j < 8; j++) {
        int i = it * 8 + j;
        tile[i][s] = x[(b * IDIM + i0 + i) * SDIM + s];
    }
    __syncthreads();
    int i2 = tid & 31, sq = tid >> 5;
#pragma unroll
    for (int j = 0; j < 8; j++) {
        int ss = sq * 8 + j;
        g_xT[(ss * BDIM + b) * IDIM + i0 + i2] = to_tf32(tile[i2][ss]);
    }
}

__global__ void k_zero_h() {
    int i = blockIdx.x * 256 + threadIdx.x;   // grid 576*256 = 147456
    if (i < BDIM * HDIM) g_hA[i] = 0.0f;
    g_hT3A[i] = 0.0f;
}

// ---------------- Gx[s] = xT[s] @ Wih^T + biases + fused Whh cvt --------------
// grid (32, 64): bm = x&1, bn = x>>1. K=256, 16 stages of 16, cp.async 2-stage.
// Post-epilogue: each CTA converts a disjoint 64-row x 512-col slab of
// Whh_enc[s] into the tiled tf32 layout g_Wt2.
__global__ __launch_bounds__(256) void k_gx(const float* __restrict__ Wih,
                                            const float* __restrict__ Whh,
                                            const float* __restrict__ bih,
                                            const float* __restrict__ bhh) {
    __shared__ float sm[2 * 5120];
    int tid = threadIdx.x;
    int s = blockIdx.y;
    int bm = blockIdx.x & 1;
    int bn = blockIdx.x >> 1;

    const float* Ag[2]; const float* Bg[2];
    uint32_t aoff[2], boff[2];
#pragma unroll
    for (int jj = 0; jj < 2; jj++) {
        int q = tid + 256 * jj;
        int r = q >> 2, kq = q & 3;
        Ag[jj] = g_xT + (size_t)(s * BDIM + bm * 128 + r) * IDIM + kq * 4;
        Bg[jj] = Wih + ((size_t)s * GE + bn * 128 + r) * IDIM + kq * 4;
        aoff[jj] = (uint32_t)(r * 20 + kq * 4) * 4;
        boff[jj] = (uint32_t)(2560 + r * 20 + kq * 4) * 4;
    }
    uint32_t sbase = (uint32_t)__cvta_generic_to_shared(sm);

    int warp = tid >> 5, lane = tid & 31;
    int g = lane >> 2, t = lane & 3;
    int m0 = (warp >> 1) * 32, n0 = (warp & 1) * 64;

    float c[2][8][4] = {};

    cpa16(sbase + aoff[0], Ag[0]); cpa16(sbase + aoff[1], Ag[1]);
    cpa16(sbase + boff[0], Bg[0]); cpa16(sbase + boff[1], Bg[1]);
    cpa_commit();

    for (int st = 0; st < 16; st++) {
        if (st + 1 < 16) {
            uint32_t so = sbase + ((st + 1) & 1) * 5120 * 4;
            cpa16(so + aoff[0], Ag[0] + (st + 1) * 16);
            cpa16(so + aoff[1], Ag[1] + (st + 1) * 16);
            cpa16(so + boff[0], Bg[0] + (st + 1) * 16);
            cpa16(so + boff[1], Bg[1] + (st + 1) * 16);
            cpa_commit();
            cpa_wait<1>();
        } else {
            cpa_wait<0>();
        }
        __syncthreads();
        int fb = (st & 1) * 5120;
#pragma unroll
        for (int kk = 0; kk < 16; kk += 8) {
            uint32_t b0[8], b1[8];
#pragma unroll
            for (int f = 0; f < 8; f++) {
                b0[f] = frna(sm[fb + 2560 + (n0 + f * 8 + g) * 20 + kk + t]);
                b1[f] = frna(sm[fb + 2560 + (n0 + f * 8 + g) * 20 + kk + t + 4]);
            }
#pragma unroll
            for (int dm = 0; dm < 2; dm++) {
                int r0 = m0 + dm * 16 + g;
                uint32_t a0 = fbits(sm[fb + r0 * 20 + kk + t]);
                uint32_t a1 = fbits(sm[fb + (r0 + 8) * 20 + kk + t]);
                uint32_t a2 = fbits(sm[fb + r0 * 20 + kk + t + 4]);
                uint32_t a3 = fbits(sm[fb + (r0 + 8) * 20 + kk + t + 4]);
#pragma unroll
                for (int f = 0; f < 8; f++)
                    mma8(c[dm][f], a0, a1, a2, a3, b0[f], b1[f]);
            }
        }
        __syncthreads();
    }
#pragma unroll
    for (int f = 0; f < 8; f++) {
        int col = bn * 128 + n0 + f * 8 + 2 * t;
        float bi0 = bih[s * GE + col] + bhh[s * GE + col];
        float bi1 = bih[s * GE + col + 1] + bhh[s * GE + col + 1];
#pragma unroll
        for (int dm = 0; dm < 2; dm++) {
            int row = bm * 128 + m0 + dm * 16 + g;
            size_t r0 = ((size_t)s * BDIM + row) * GE + col;
            size_t r1 = ((size_t)s * BDIM + row + 8) * GE + col;
            *(float2*)&g_Gx[r0] = make_float2(c[dm][f][0] + bi0, c[dm][f][1] + bi1);
            *(float2*)&g_Gx[r1] = make_float2(c[dm][f][2] + bi0, c[dm][f][3] + bi1);
        }
    }

    // ---- fused Whh -> g_Wt2 tiled tf32 conversion (64 rows x 512 cols) ----
    {
        int chunk = bm * 16 + bn;                 // 0..31, rows [chunk*64, +64)
        const float* Ws = Whh + (size_t)s * GE * HDIM;
        float* Dt = g_Wt2 + (size_t)s * 32 * 16 * 2304;
#pragma unroll 4
        for (int j = 0; j < 32; j++) {
            int fid = j * 256 + tid;              // float4 id over 64x128
            int r   = fid >> 7;                   // 0..63
            int c4  = fid & 127;
            int gr  = chunk * 64 + r;             // raw gate-row 0..2047
            int col0 = c4 * 4;
            float4 v = *(const float4*)&Ws[(size_t)gr * HDIM + col0];
            int gate = gr >> 9;
            int hcol = gr & 511;
            int bh = hcol >> 4;
            int r16 = hcol & 15;
            int stg = col0 >> 5;
            int cc  = col0 & 31;
            size_t di = ((size_t)bh * 16 + stg) * 2304 + (gate * 16 + r16) * 36 + cc;
            *(float4*)&Dt[di] = cvt4(v);
        }
    }
}

// ---------------- encoder step v6: 256 CTAs of 32x64, 2 CTAs/SM ---------------
// grid 256 = bm(8 x 32 rows) x bh(32 x [4 gates x 16 hc]). K=512 -> 16 stages
// of K=32. Slot: A 32x36 (4608B) + B 64x36 (9216B) = 13824B; 4-slot ring =
// 55296B dynamic -> 2 CTAs/SM. Warp tile 16x16 (8 warps).
#define ESLOT 3456   // floats per ring slot (A 1152 + B 2304)
__global__ __launch_bounds__(256) void k_enc_step(int s) {
    extern __shared__ float sm[];
    __shared__ uint64_t mbar_s[4];
    int tid = threadIdx.x;
    int bm = blockIdx.x & 7;
    int bh = blockIdx.x >> 3;

    const float* hT3in = (s & 1) ? g_hT3B : g_hT3A;
    float* hT3out      = (s & 1) ? g_hT3A : g_hT3B;
    const float* hin   = (s & 1) ? g_hB : g_hA;
    float* hout        = (s & 1) ? g_hA : g_hB;

    const float* Abase = hT3in + (size_t)bm * 16 * 1152;               // [st][32][36]
    const float* Bbase = g_Wt2 + (((size_t)s * 32 + bh) * 16) * 2304;  // [st][64][36]

    uint32_t smb = (uint32_t)__cvta_generic_to_shared(sm);
    uint32_t mb0 = (uint32_t)__cvta_generic_to_shared(mbar_s);

    if (tid == 0) {
#pragma unroll
        for (int p = 0; p < 4; p++) mbar_init(mb0 + p * 8, 1);
    }
    __syncthreads();
    if (tid == 0) {
#pragma unroll
        for (int p = 0; p < 4; p++) {
            uint32_t mb = mb0 + p * 8;
            mbar_expect_tx(mb, 13824);
            bulk_g2s(smb + p * ESLOT * 4,        Abase + p * 1152, 4608, mb);
            bulk_g2s(smb + p * ESLOT * 4 + 4608, Bbase + p * 2304, 9216, mb);
        }
    }

    int warp = tid >> 5, lane = tid & 31;
    int m0 = (warp >> 2) * 16;          // 2 m-tiles of 16
    int n0 = (warp & 3) * 16;           // 4 n-tiles of 16
    int g = lane >> 2, t = lane & 3;

    float c[2][4] = {};

    for (int st = 0; st < 16; st++) {
        mbar_wait(mb0 + (st & 3) * 8, (st >> 2) & 1);
        int ab = (st & 3) * ESLOT;
        int bb = ab + 1152;
#pragma unroll
        for (int kc = 0; kc < 32; kc += 8) {
            uint32_t a0 = fbits(sm[ab + (m0 + g) * 36 + kc + t]);
            uint32_t a1 = fbits(sm[ab + (m0 + g + 8) * 36 + kc + t]);
            uint32_t a2 = fbits(sm[ab + (m0 + g) * 36 + kc + t + 4]);
            uint32_t a3 = fbits(sm[ab + (m0 + g + 8) * 36 + kc + t + 4]);
#pragma unroll
            for (int f = 0; f < 2; f++) {
                int rb = n0 + f * 8 + g;
                uint32_t b0 = fbits(sm[bb + rb * 36 + kc + t]);
                uint32_t b1 = fbits(sm[bb + rb * 36 + kc + t + 4]);
                mma8(c[f], a0, a1, a2, a3, b0, b1);
            }
        }
        __syncthreads();
        if (tid == 0 && st + 4 < 16) {
            uint32_t mb = mb0 + (st & 3) * 8;
            mbar_expect_tx(mb, 13824);
            bulk_g2s(smb + (st & 3) * ESLOT * 4,        Abase + (st + 4) * 1152, 4608, mb);
            bulk_g2s(smb + (st & 3) * ESLOT * 4 + 4608, Bbase + (st + 4) * 2304, 9216, mb);
        }
    }

    // accumulators -> Cs (32 x 68 = 2176 floats; aliases slot 0, free now)
#pragma unroll
    for (int f = 0; f < 2; f++) {
        int col0 = n0 + f * 8 + 2 * t;
        *(float2*)&sm[(m0 + g) * 68 + col0]     = make_float2(c[f][0], c[f][1]);
        *(float2*)&sm[(m0 + g + 8) * 68 + col0] = make_float2(c[f][2], c[f][3]);
    }
    __syncthreads();

    // fused LSTM pointwise + elu: 2 elems/thread (32 rows x 16 hcols)
    int row = tid >> 3;             // 0..31
    int hc0 = (tid & 7) * 2;        // 0..14
    int grow = bm * 32 + row;
    int gcol = bh * 16 + hc0;
    const float* Gxp = g_Gx + ((size_t)s * BDIM + grow) * GE + gcol;
    float2 gi = *(float2*)&sm[row * 68 + 0 * 16 + hc0];
    float2 gf = *(float2*)&sm[row * 68 + 1 * 16 + hc0];
    float2 gg = *(float2*)&sm[row * 68 + 2 * 16 + hc0];
    float2 go = *(float2*)&sm[row * 68 + 3 * 16 + hc0];
    float2 xi = *(const float2*)(Gxp + 0 * HDIM);
    float2 xf = *(const float2*)(Gxp + 1 * HDIM);
    float2 xg = *(const float2*)(Gxp + 2 * HDIM);
    float2 xo = *(const float2*)(Gxp + 3 * HDIM);
    float2 hp = *(const float2*)&hin[(size_t)grow * HDIM + gcol];
    float2 hv, tv, ev;
#pragma unroll
    for (int q = 0; q < 2; q++) {
        float vi = (&gi.x)[q] + (&xi.x)[q];
        float vf = (&gf.x)[q] + (&xf.x)[q];
        float vg = (&gg.x)[q] + (&xg.x)[q];
        float vo = (&go.x)[q] + (&xo.x)[q];
        float cc = sigf(vf) * (&hp.x)[q] + sigf(vi) * tanhf(vg);
        float hn = sigf(vo) * tanhf(cc);
        (&hv.x)[q] = hn;
        (&tv.x)[q] = to_tf32(hn);
        (&ev.x)[q] = hn > 0.0f ? hn : expm1f(hn);
    }
    *(float2*)&hout[(size_t)grow * HDIM + gcol] = hv;
    *(float2*)&g_enc[(size_t)s * BDIM * HDIM + (size_t)grow * HDIM + gcol] = ev;
    // tiled tf32 h for next step's A bulks: [bm8][stage][32 rows][36]
    size_t tvo = ((size_t)(bm * 16 + (bh >> 1)) * 32 + row) * 36 + (bh & 1) * 16 + hc0;
    *(float2*)&hT3out[tvo] = tv;
}

// ---------------- strided residual chain --------------------------------------
__global__ void k_chain() {
    int e = blockIdx.x * 256 + threadIdx.x;
    float prev = g_enc[60 * BDIM * HDIM + e];
#pragma unroll
    for (int k = 0; k < 16; k++) {
        int off = (k * 4) * BDIM * HDIM + e;
        float v = 0.5f * g_enc[off] + 0.5f * prev;
        g_enc[off] = v;
        prev = v;
    }
}

// ---------------- decoder GEMM: enc_rev @ Wih_dec^T (i,g,o), big tiles --------
__global__ __launch_bounds__(256) void k_dec_gemm(const float* __restrict__ Wd) {
    __shared__ float sm[2 * 5120];
    int tid = threadIdx.x;
    int sd = blockIdx.y;
    int bm = blockIdx.x & 1;
    int bn = blockIdx.x >> 1;
    const int agate[3] = {0, 2, 3};
    int grow0 = agate[bn >> 1] * IDIM + (bn & 1) * 128;

    const float* Ag[2]; const float* Bg[2];
    uint32_t aoff[2], boff[2];
#pragma unroll
    for (int jj = 0; jj < 2; jj++) {
        int q = tid + 256 * jj;
        int r = q >> 2, kq = q & 3;
        Ag[jj] = g_enc + ((size_t)(63 - sd) * BDIM + bm * 128 + r) * HDIM + kq * 4;
        Bg[jj] = Wd + ((size_t)sd * GD + grow0 + r) * HDIM + kq * 4;
        aoff[jj] = (uint32_t)(r * 20 + kq * 4) * 4;
        boff[jj] = (uint32_t)(2560 + r * 20 + kq * 4) * 4;
    }
    uint32_t sbase = (uint32_t)__cvta_generic_to_shared(sm);

    int warp = tid >> 5, lane = tid & 31;
    int g = lane >> 2, t = lane & 3;
    int m0 = (warp >> 1) * 32, n0 = (warp & 1) * 64;

    float c[2][8][4] = {};

    cpa16(sbase + aoff[0], Ag[0]); cpa16(sbase + aoff[1], Ag[1]);
    cpa16(sbase + boff[0], Bg[0]); cpa16(sbase + boff[1], Bg[1]);
    cpa_commit();

    for (int st = 0; st < 32; st++) {
        if (st + 1 < 32) {
            uint32_t so = sbase + ((st + 1) & 1) * 5120 * 4;
            cpa16(so + aoff[0], Ag[0] + (st + 1) * 16);
            cpa16(so + aoff[1], Ag[1] + (st + 1) * 16);
            cpa16(so + boff[0], Bg[0] + (st + 1) * 16);
            cpa16(so + boff[1], Bg[1] + (st + 1) * 16);
            cpa_commit();
            cpa_wait<1>();
        } else {
            cpa_wait<0>();
        }
        __syncthreads();
        int fb = (st & 1) * 5120;
#pragma unroll
        for (int kk = 0; kk < 16; kk += 8) {
            uint32_t b0[8], b1[8];
#pragma unroll
            for (int f = 0; f < 8; f++) {
                b0[f] = frna(sm[fb + 2560 + (n0 + f * 8 + g) * 20 + kk + t]);
                b1[f] = frna(sm[fb + 2560 + (n0 + f * 8 + g) * 20 + kk + t + 4]);
            }
#pragma unroll
            for (int dm = 0; dm < 2; dm++) {
                int r0 = m0 + dm * 16 + g;
                uint32_t a0 = frna(sm[fb + r0 * 20 + kk + t]);
                uint32_t a1 = frna(sm[fb + (r0 + 8) * 20 + kk + t]);
                uint32_t a2 = frna(sm[fb + r0 * 20 + kk + t + 4]);
                uint32_t a3 = frna(sm[fb + (r0 + 8) * 20 + kk + t + 4]);
#pragma unroll
                for (int f = 0; f < 8; f++)
                    mma8(c[dm][f], a0, a1, a2, a3, b0[f], b1[f]);
            }
        }
        __syncthreads();
    }
#pragma unroll
    for (int f = 0; f < 8; f++) {
        int col = bn * 128 + n0 + f * 8 + 2 * t;
#pragma unroll
        for (int dm = 0; dm < 2; dm++) {
            int row = bm * 128 + m0 + dm * 16 + g;
            size_t r0 = ((size_t)sd * BDIM + row) * 768 + col;
            size_t r1 = ((size_t)sd * BDIM + row + 8) * 768 + col;
            *(float2*)&g_dg[r0] = make_float2(c[dm][f][0], c[dm][f][1]);
            *(float2*)&g_dg[r1] = make_float2(c[dm][f][2], c[dm][f][3]);
        }
    }
}

// ---------------- decoder pointwise: biases + activations ---------------------
__global__ __launch_bounds__(256) void k_dec_pw(const float* __restrict__ bid,
                                                const float* __restrict__ bhd) {
    int idx = blockIdx.x * 256 + threadIdx.x;
    int icg = idx & 63;
    int row = (idx >> 6) & 255;
    int sd  = idx >> 14;
    int ic  = icg * 4;
    size_t base = ((size_t)sd * BDIM + row) * 768;
    float4 vi = *(const float4*)&g_dg[base + 0 * IDIM + ic];
    float4 vg = *(const float4*)&g_dg[base + 1 * IDIM + ic];
    float4 vo = *(const float4*)&g_dg[base + 2 * IDIM + ic];
    const float* B1 = bid + sd * GD;
    const float* B2 = bhd + sd * GD;
    float4 bi1 = *(const float4*)&B1[0 * IDIM + ic];
    float4 bi2 = *(const float4*)&B2[0 * IDIM + ic];
    float4 bg1 = *(const float4*)&B1[2 * IDIM + ic];
    float4 bg2 = *(const float4*)&B2[2 * IDIM + ic];
    float4 bo1 = *(const float4*)&B1[3 * IDIM + ic];
    float4 bo2 = *(const float4*)&B2[3 * IDIM + ic];
    float4 ov;
#pragma unroll
    for (int q = 0; q < 4; q++) {
        float gi = (&vi.x)[q] + (&bi1.x)[q] + (&bi2.x)[q];
        float gg = (&vg.x)[q] + (&bg1.x)[q] + (&bg2.x)[q];
        float go = (&vo.x)[q] + (&bo1.x)[q] + (&bo2.x)[q];
        float cc = sigf(gi) * tanhf(gg);
        (&ov.x)[q] = sigf(go) * tanhf(cc);
    }
    *(float4*)&g_hd[((size_t)sd * BDIM + row) * IDIM + ic] = ov;
}

// ---------------- cumsum(4) + tanh + reverse + transpose to (B,I,S) -----------
__global__ void k_final(float* __restrict__ out) {
    int idx = blockIdx.x * 256 + threadIdx.x;
    int i = idx & 255;
    int q = (idx >> 8) & 15;
    int b = idx >> 12;
    int base = (4 * q * BDIM + b) * IDIM + i;
    float a0 = g_hd[base];
    float a1 = g_hd[base + 1 * BDIM * IDIM];
    float a2 = g_hd[base + 2 * BDIM * IDIM];
    float a3 = g_hd[base + 3 * BDIM * IDIM];
    float r0 = a0, r1 = r0 + a1, r2 = r1 + a2, r3 = r2 + a3;
    float4 v = make_float4(tanhf(r3), tanhf(r2), tanhf(r1), tanhf(r0));
    *(float4*)(out + (size_t)(b * IDIM + i) * SDIM + (60 - 4 * q)) = v;
}

// ---------------- launch ------------------------------------------------------
extern "C" void kernel_launch(void* const* d_in, const int* in_sizes, int n_in,
                              void* d_out, int out_size) {
    const float* x       = (const float*)d_in[0];
    const float* Wih_enc = (const float*)d_in[1];
    const float* Whh_enc = (const float*)d_in[2];
    const float* bih_enc = (const float*)d_in[3];
    const float* bhh_enc = (const float*)d_in[4];
    const float* Wih_dec = (const float*)d_in[5];
    // d_in[6] = Whh_dec: unused by the reference computation
    const float* bih_dec = (const float*)d_in[7];
    const float* bhh_dec = (const float*)d_in[8];
    float* out = (float*)d_out;

    cudaFuncSetAttribute(k_enc_step, cudaFuncAttributeMaxDynamicSharedMemorySize,
                         4 * ESLOT * 4);

    k_transpose_x<<<2048, 256>>>(x);
    k_zero_h<<<576, 256>>>();
    k_gx<<<dim3(32, 64), 256>>>(Wih_enc, Whh_enc, bih_enc, bhh_enc);
    for (int s = 0; s < SDIM; s++) {
        k_enc_step<<<256, 256, 4 * ESLOT * 4>>>(s);
    }
    k_chain<<<512, 256>>>();
    k_dec_gemm<<<dim3(12, 64), 256>>>(Wih_dec);
    k_dec_pw<<<4096, 256>>>(bih_dec, bhh_dec);
    k_final<<<4096, 256>>>(out);
}